// round 11
// baseline (speedup 1.0000x reference)
#include <cuda_runtime.h>
#include <math.h>
#include <stdint.h>

#define NN    50000      // total nodes
#define NPG   6250       // nodes per graph
#define BG    8          // graphs
#define EE    800000     // total edges
#define CIN   512
#define HH    256
#define HH3   768
#define KSEL  5000
#define RANK_BPG 782     // ceil(6250/8) blocks per graph for rank kernel

typedef unsigned long long ull;

// ----------------------------- scratch (static device memory) ---------------
__device__ int   g_is64;
__device__ float g_deg[NN];
__device__ int   g_cnt[NN];
__device__ int   g_rowptr[NN + 1];
__device__ int   g_fill[NN];
__device__ int   g_bsum[64];
__device__ int   g_esrc[EE];
__device__ float g_enorm[EE];
__device__ float g_xw[(size_t)NN * HH];     // 51 MB
__device__ float g_cat[(size_t)NN * HH3];   // 154 MB, [x1|x2|x3]
__device__ float g_score[NN];
__device__ unsigned char g_keep[NN];
__device__ float g_pwn[HH3];
__device__ float g_psum[384 * 256];
__device__ float g_pmax[384 * 256];
__device__ float g_ro[BG * 2 * HH3];

// ----------------------------- f32x2 helpers ---------------------------------
__device__ __forceinline__ uint32_t smem_u32(const void* p) {
    uint32_t a;
    asm("{ .reg .u64 t; cvta.to.shared.u64 t, %1; cvt.u32.u64 %0, t; }" : "=r"(a) : "l"(p));
    return a;
}
__device__ __forceinline__ void ffma2(ull& d, ull a, ull b) {
    asm("fma.rn.f32x2 %0, %1, %2, %0;" : "+l"(d) : "l"(a), "l"(b));
}
__device__ __forceinline__ ull dup2(float x) {
    ull r;
    asm("mov.b64 %0, {%1, %1};" : "=l"(r) : "f"(x));
    return r;
}
__device__ __forceinline__ ull lds64(uint32_t addr) {
    ull r;
    asm volatile("ld.shared.b64 %0, [%1];" : "=l"(r) : "r"(addr));
    return r;
}
__device__ __forceinline__ void unpack2(float& lo, float& hi, ull v) {
    asm("mov.b64 {%0, %1}, %2;" : "=f"(lo), "=f"(hi) : "l"(v));
}

// ----------------------------- dtype probe + init -----------------------------
__global__ void k_initprobe(const int* __restrict__ ei32) {
    int i = blockIdx.x * blockDim.x + threadIdx.x;
    if (i < NN) { g_deg[i] = 0.f; g_cnt[i] = 0; g_fill[i] = 0; }
    if (blockIdx.x == 0) {
        __shared__ int nz;
        if (threadIdx.x == 0) nz = 0;
        __syncthreads();
        int any = 0;
        for (int j = 1 + 2 * threadIdx.x; j < 4096; j += 2 * blockDim.x)
            if (ei32[j] != 0) any = 1;
        if (any) atomicAdd(&nz, 1);
        __syncthreads();
        if (threadIdx.x == 0) g_is64 = (nz == 0) ? 1 : 0;
    }
}

__device__ __forceinline__ int load_edge(const void* ei, int which, int e) {
    if (g_is64) return (int)((const long long*)ei)[(size_t)which * EE + e];
    return ((const int*)ei)[which * EE + e];
}

// ----------------------------- setup kernels --------------------------------
__global__ void k_degcnt(const void* __restrict__ ei, const float* __restrict__ ea) {
    int e = blockIdx.x * blockDim.x + threadIdx.x;
    if (e < EE) {
        int d = load_edge(ei, 1, e);
        if ((unsigned)d < NN) {
            atomicAdd(&g_deg[d], ea[e]);
            atomicAdd(&g_cnt[d], 1);
        }
    }
}

__global__ void k_scan1() {
    __shared__ int sm[1024];
    int i = blockIdx.x * 1024 + threadIdx.x;
    int v = (i < NN) ? g_cnt[i] : 0;
    sm[threadIdx.x] = v;
    __syncthreads();
    for (int off = 1; off < 1024; off <<= 1) {
        int t = (threadIdx.x >= off) ? sm[threadIdx.x - off] : 0;
        __syncthreads();
        sm[threadIdx.x] += t;
        __syncthreads();
    }
    if (i < NN) g_rowptr[i] = sm[threadIdx.x] - v;
    if (threadIdx.x == 1023) g_bsum[blockIdx.x] = sm[1023];
}

__global__ void k_scan2() {
    __shared__ int sm[64];
    int t = threadIdx.x;
    int v = (t < 49) ? g_bsum[t] : 0;
    sm[t] = v;
    __syncthreads();
    for (int off = 1; off < 64; off <<= 1) {
        int u = (t >= off) ? sm[t - off] : 0;
        __syncthreads();
        sm[t] += u;
        __syncthreads();
    }
    if (t < 49) g_bsum[t] = sm[t] - v;
}

__global__ void k_scan3() {
    int i = blockIdx.x * blockDim.x + threadIdx.x;
    if (i < NN) g_rowptr[i] += g_bsum[i >> 10];
    if (i == 0) g_rowptr[NN] = EE;
}

__global__ void k_fill(const void* __restrict__ ei, const float* __restrict__ ea) {
    int e = blockIdx.x * blockDim.x + threadIdx.x;
    if (e < EE) {
        int s = load_edge(ei, 0, e);
        int d = load_edge(ei, 1, e);
        if ((unsigned)s < NN && (unsigned)d < NN) {
            int pos = g_rowptr[d] + atomicAdd(&g_fill[d], 1);
            float ds = rsqrtf(g_deg[s] + 1.0f);
            float dd = rsqrtf(g_deg[d] + 1.0f);
            g_esrc[pos]  = s;
            g_enorm[pos] = ds * ea[e] * dd;
        }
    }
}

// ----------------------------- FFMA2 SGEMM: C = A[M,Kdim] * B[Kdim,256] ------
// CTA tile 128x128, thread tile 8x8, K-step 16, DOUBLE-BUFFERED smem (one
// __syncthreads per chunk), global prefetch in regs overlapping the FMA block.
__global__ __launch_bounds__(256, 2) void k_gemm2(
    const float* __restrict__ Aext, int use_cat, int cat_off,
    int lda, int Kdim, const float* __restrict__ B)
{
    const float* A = use_cat ? (g_cat + cat_off) : Aext;
    __shared__ __align__(16) float As[2][16][128];
    __shared__ __align__(16) float Bs[2][16][128];
    int tid = threadIdx.x;
    int bm = blockIdx.y, bn = blockIdx.x;
    int tx = tid & 15, ty = tid >> 4;
    uint32_t bs_b = smem_u32(Bs);

    ull acc2[8][4];
    #pragma unroll
    for (int i = 0; i < 8; i++)
        #pragma unroll
        for (int j = 0; j < 4; j++) acc2[i][j] = 0ull;

    int arow0 = tid >> 2,         akq = tid & 3;      // (256+tid)&3 == tid&3
    int arow1 = (256 + tid) >> 2;
    int grow0 = bm * 128 + arow0, grow1 = bm * 128 + arow1;
    bool aok0 = grow0 < NN, aok1 = grow1 < NN;
    int bkr0 = tid >> 5,          bnc = (tid & 31) * 4;
    int bkr1 = (256 + tid) >> 5;                      // 8 + (tid>>5)

    const float* Ap0 = A + (size_t)grow0 * lda + akq * 4;
    const float* Ap1 = A + (size_t)grow1 * lda + akq * 4;
    const float* Bp0 = B + (size_t)bkr0 * HH + bn * 128 + bnc;
    const float* Bp1 = B + (size_t)bkr1 * HH + bn * 128 + bnc;

    float4 pa0, pa1, pb0, pb1;
    #define GLOAD(k0)                                                        \
        pa0 = aok0 ? *(const float4*)(Ap0 + (k0)) : make_float4(0.f,0.f,0.f,0.f); \
        pa1 = aok1 ? *(const float4*)(Ap1 + (k0)) : make_float4(0.f,0.f,0.f,0.f); \
        pb0 = *(const float4*)(Bp0 + (size_t)(k0) * HH);                     \
        pb1 = *(const float4*)(Bp1 + (size_t)(k0) * HH)
    #define SSTORE(st)                                                       \
        As[st][akq * 4 + 0][arow0] = pa0.x;                                  \
        As[st][akq * 4 + 1][arow0] = pa0.y;                                  \
        As[st][akq * 4 + 2][arow0] = pa0.z;                                  \
        As[st][akq * 4 + 3][arow0] = pa0.w;                                  \
        As[st][akq * 4 + 0][arow1] = pa1.x;                                  \
        As[st][akq * 4 + 1][arow1] = pa1.y;                                  \
        As[st][akq * 4 + 2][arow1] = pa1.z;                                  \
        As[st][akq * 4 + 3][arow1] = pa1.w;                                  \
        *(float4*)&Bs[st][bkr0][bnc] = pb0;                                  \
        *(float4*)&Bs[st][bkr1][bnc] = pb1

    GLOAD(0);
    SSTORE(0);
    __syncthreads();

    int nC = Kdim >> 4;
    for (int c = 0; c < nC; c++) {
        if (c + 1 < nC) { GLOAD((c + 1) * 16); }      // LDGs overlap FMA block
        int s = c & 1;
        uint32_t bbase = bs_b + (uint32_t)s * 8192;
        #pragma unroll
        for (int k = 0; k < 16; k++) {
            float ar[8];
            *(float4*)&ar[0] = *(const float4*)&As[s][k][ty * 8];
            *(float4*)&ar[4] = *(const float4*)&As[s][k][ty * 8 + 4];
            ull br2[4];
            uint32_t ba = bbase + (uint32_t)(k * 128 + tx * 8) * 4;
            #pragma unroll
            for (int j = 0; j < 4; j++) br2[j] = lds64(ba + j * 8);
            #pragma unroll
            for (int i = 0; i < 8; i++) {
                ull a2 = dup2(ar[i]);
                #pragma unroll
                for (int j = 0; j < 4; j++)
                    ffma2(acc2[i][j], a2, br2[j]);
            }
        }
        if (c + 1 < nC) { SSTORE((c + 1) & 1); }      // idle stage, no hazard
        __syncthreads();
    }
    #undef GLOAD
    #undef SSTORE

    #pragma unroll
    for (int i = 0; i < 8; i++) {
        int row = bm * 128 + ty * 8 + i;
        if (row < NN) {
            float c[8];
            #pragma unroll
            for (int j = 0; j < 4; j++) unpack2(c[2 * j], c[2 * j + 1], acc2[i][j]);
            float* Cp = g_xw + (size_t)row * HH + bn * 128 + tx * 8;
            *(float4*)Cp       = make_float4(c[0], c[1], c[2], c[3]);
            *(float4*)(Cp + 4) = make_float4(c[4], c[5], c[6], c[7]);
        }
    }
}

// ----------------------------- CSR gather-aggregate + bias + relu -----------
// Lane owns 8 consecutive columns (float4 x2). do_score!=0: fused TopK score.
__global__ void k_agg(const float* __restrict__ bias, int out_off, int do_score) {
    int warp = (blockIdx.x * 256 + threadIdx.x) >> 5;
    int lane = threadIdx.x & 31;
    if (warp >= NN) return;
    int n = warp;
    float di = rsqrtf(g_deg[n] + 1.0f);
    float d2 = di * di;
    const float4* xr = (const float4*)(g_xw + (size_t)n * HH);
    float4 v0 = xr[lane * 2], v1 = xr[lane * 2 + 1];
    float4 A0 = make_float4(d2 * v0.x, d2 * v0.y, d2 * v0.z, d2 * v0.w);
    float4 A1 = make_float4(d2 * v1.x, d2 * v1.y, d2 * v1.z, d2 * v1.w);

    int e0 = g_rowptr[n], e1 = g_rowptr[n + 1];
    int e = e0;
    for (; e + 1 < e1; e += 2) {
        int s0 = g_esrc[e],    s1 = g_esrc[e + 1];
        float w0 = g_enorm[e], w1 = g_enorm[e + 1];
        const float4* r0 = (const float4*)(g_xw + (size_t)s0 * HH);
        const float4* r1 = (const float4*)(g_xw + (size_t)s1 * HH);
        float4 p0 = r0[lane * 2], p1 = r0[lane * 2 + 1];
        float4 q0 = r1[lane * 2], q1 = r1[lane * 2 + 1];
        A0.x = fmaf(w0, p0.x, A0.x); A0.y = fmaf(w0, p0.y, A0.y);
        A0.z = fmaf(w0, p0.z, A0.z); A0.w = fmaf(w0, p0.w, A0.w);
        A1.x = fmaf(w0, p1.x, A1.x); A1.y = fmaf(w0, p1.y, A1.y);
        A1.z = fmaf(w0, p1.z, A1.z); A1.w = fmaf(w0, p1.w, A1.w);
        A0.x = fmaf(w1, q0.x, A0.x); A0.y = fmaf(w1, q0.y, A0.y);
        A0.z = fmaf(w1, q0.z, A0.z); A0.w = fmaf(w1, q0.w, A0.w);
        A1.x = fmaf(w1, q1.x, A1.x); A1.y = fmaf(w1, q1.y, A1.y);
        A1.z = fmaf(w1, q1.z, A1.z); A1.w = fmaf(w1, q1.w, A1.w);
    }
    if (e < e1) {
        int s = g_esrc[e];
        float w = g_enorm[e];
        const float4* r0 = (const float4*)(g_xw + (size_t)s * HH);
        float4 p0 = r0[lane * 2], p1 = r0[lane * 2 + 1];
        A0.x = fmaf(w, p0.x, A0.x); A0.y = fmaf(w, p0.y, A0.y);
        A0.z = fmaf(w, p0.z, A0.z); A0.w = fmaf(w, p0.w, A0.w);
        A1.x = fmaf(w, p1.x, A1.x); A1.y = fmaf(w, p1.y, A1.y);
        A1.z = fmaf(w, p1.z, A1.z); A1.w = fmaf(w, p1.w, A1.w);
    }
    const float4* b4 = (const float4*)bias;
    float4 B0 = b4[lane * 2], B1 = b4[lane * 2 + 1];
    A0.x = fmaxf(A0.x + B0.x, 0.f); A0.y = fmaxf(A0.y + B0.y, 0.f);
    A0.z = fmaxf(A0.z + B0.z, 0.f); A0.w = fmaxf(A0.w + B0.w, 0.f);
    A1.x = fmaxf(A1.x + B1.x, 0.f); A1.y = fmaxf(A1.y + B1.y, 0.f);
    A1.z = fmaxf(A1.z + B1.z, 0.f); A1.w = fmaxf(A1.w + B1.w, 0.f);
    float4* orow = (float4*)(g_cat + (size_t)n * HH3 + out_off);
    orow[lane * 2]     = A0;
    orow[lane * 2 + 1] = A1;

    if (do_score) {
        const float4* pw4 = (const float4*)g_pwn;
        // x3 part (cols 512..767) from registers
        float4 W0 = pw4[128 + lane * 2], W1 = pw4[128 + lane * 2 + 1];
        float s = A0.x * W0.x;
        s = fmaf(A0.y, W0.y, s); s = fmaf(A0.z, W0.z, s); s = fmaf(A0.w, W0.w, s);
        s = fmaf(A1.x, W1.x, s); s = fmaf(A1.y, W1.y, s);
        s = fmaf(A1.z, W1.z, s); s = fmaf(A1.w, W1.w, s);
        // x1,x2 parts (cols 0..511) from g_cat
        const float4* cr = (const float4*)(g_cat + (size_t)n * HH3);
        #pragma unroll
        for (int j = 0; j < 4; j++) {
            float4 cv = cr[j * 32 + lane];
            float4 pv = pw4[j * 32 + lane];
            s = fmaf(cv.x, pv.x, s); s = fmaf(cv.y, pv.y, s);
            s = fmaf(cv.z, pv.z, s); s = fmaf(cv.w, pv.w, s);
        }
        #pragma unroll
        for (int o = 16; o; o >>= 1) s += __shfl_xor_sync(0xffffffffu, s, o);
        if (lane == 0) g_score[n] = 1.f / (1.f + expf(-s));
    }
}

// ----------------------------- pooling score vector --------------------------
__global__ void k_pwn(const float* __restrict__ pw) {
    __shared__ float red[8];
    __shared__ float s_inv;
    int tid = threadIdx.x;
    float s = 0.f;
    for (int i = tid; i < HH3; i += 256) { float v = pw[i]; s += v * v; }
    #pragma unroll
    for (int o = 16; o; o >>= 1) s += __shfl_xor_sync(0xffffffffu, s, o);
    if ((tid & 31) == 0) red[tid >> 5] = s;
    __syncthreads();
    if (tid == 0) {
        float tot = 0.f;
        for (int i = 0; i < 8; i++) tot += red[i];
        s_inv = rsqrtf(tot);
    }
    __syncthreads();
    for (int i = tid; i < HH3; i += 256) g_pwn[i] = pw[i] * s_inv;
}

// exact top-K selection via rank counting (matches jax top_k tie semantics)
__global__ void k_rank() {
    __shared__ float ss[NPG];
    int g  = blockIdx.x / RANK_BPG;
    int bb = blockIdx.x % RANK_BPG;
    for (int i = threadIdx.x; i < NPG; i += 256) ss[i] = g_score[g * NPG + i];
    __syncthreads();
    int wi = threadIdx.x >> 5, lane = threadIdx.x & 31;
    int i = bb * 8 + wi;
    if (i >= NPG) return;
    float si = ss[i];
    int cnt = 0;
    for (int j0 = 0; j0 < NPG; j0 += 32) {
        int j = j0 + lane;
        bool p = false;
        if (j < NPG) {
            float sj = ss[j];
            p = (sj > si) || (sj == si && j < i);
        }
        cnt += __popc(__ballot_sync(0xffffffffu, p));
    }
    if (lane == 0) g_keep[g * NPG + i] = (cnt < KSEL) ? 1 : 0;
}

// ----------------------------- readout (mean + max over selected) -----------
__global__ void k_readout1() {
    int b  = blockIdx.x;        // b = g*48 + cb*16 + ch
    int g  = b / 48;
    int cb = (b / 16) % 3;
    int ch = b % 16;
    int col = cb * 256 + threadIdx.x;
    int i0 = ch * 391, i1 = min(NPG, i0 + 391);
    float sum = 0.f, mx = -3.402823e38f;
    for (int i = i0; i < i1; i++) {
        int n = g * NPG + i;
        if (g_keep[n]) {
            float s = g_score[n];
            float v = s * g_cat[(size_t)n * HH3 + col];
            sum += v;
            mx = fmaxf(mx, v);
        }
    }
    g_psum[b * 256 + threadIdx.x] = sum;
    g_pmax[b * 256 + threadIdx.x] = mx;
}

__global__ void k_readout2() {
    int b = blockIdx.x;
    int g = b / 3, cb = b % 3;
    int col = cb * 256 + threadIdx.x;
    float sum = 0.f, mx = -3.402823e38f;
    for (int ch = 0; ch < 16; ch++) {
        int idx = ((g * 3 + cb) * 16 + ch) * 256 + threadIdx.x;
        sum += g_psum[idx];
        mx = fmaxf(mx, g_pmax[idx]);
    }
    g_ro[g * 2 * HH3 + col]       = sum * (1.0f / KSEL);
    g_ro[g * 2 * HH3 + HH3 + col] = mx;
}

// ----------------------------- MLP head -------------------------------------
__global__ void k_mlp(const float* __restrict__ lw1, const float* __restrict__ lb1,
                      const float* __restrict__ lw2, const float* __restrict__ lb2,
                      const float* __restrict__ lw3, const float* __restrict__ lb3,
                      float* __restrict__ out) {
    __shared__ float ro[2 * HH3];
    __shared__ float h1[HH];
    __shared__ float h2[HH / 2];
    int g = blockIdx.x, tid = threadIdx.x;
    for (int i = tid; i < 2 * HH3; i += 256) ro[i] = g_ro[g * 2 * HH3 + i];
    __syncthreads();
    float a0 = 0.f, a1 = 0.f, a2 = 0.f, a3 = 0.f;
    for (int k = 0; k < 2 * HH3; k += 4) {
        a0 = fmaf(ro[k + 0], lw1[(k + 0) * HH + tid], a0);
        a1 = fmaf(ro[k + 1], lw1[(k + 1) * HH + tid], a1);
        a2 = fmaf(ro[k + 2], lw1[(k + 2) * HH + tid], a2);
        a3 = fmaf(ro[k + 3], lw1[(k + 3) * HH + tid], a3);
    }
    h1[tid] = fmaxf(a0 + a1 + a2 + a3 + lb1[tid], 0.f);
    __syncthreads();
    if (tid < HH / 2) {
        float b0 = 0.f, b1v = 0.f;
        for (int k = 0; k < HH; k += 2) {
            b0  = fmaf(h1[k],     lw2[k * (HH / 2) + tid],       b0);
            b1v = fmaf(h1[k + 1], lw2[(k + 1) * (HH / 2) + tid], b1v);
        }
        h2[tid] = fmaxf(b0 + b1v + lb2[tid], 0.f);
    }
    __syncthreads();
    if (tid < 3) {
        float s = lb3[tid];
        for (int k = 0; k < HH / 2; k++) s = fmaf(h2[k], lw3[k * 3 + tid], s);
        out[g * 3 + tid] = s;
    }
}

// ----------------------------- launch ---------------------------------------
extern "C" void kernel_launch(void* const* d_in, const int* in_sizes, int n_in,
                              void* d_out, int out_size) {
    const float* x   = (const float*)d_in[0];
    const void*  ei  = d_in[1];              // int32 or int64 (probed at runtime)
    const float* ea  = (const float*)d_in[2];
    // d_in[3] = batch (unused): graph id = node / NPG
    const float* W1  = (const float*)d_in[4];
    const float* b1  = (const float*)d_in[5];
    const float* W2  = (const float*)d_in[6];
    const float* b2  = (const float*)d_in[7];
    const float* pw  = (const float*)d_in[8];
    const float* lw1 = (const float*)d_in[9];
    const float* lb1 = (const float*)d_in[10];
    const float* lw2 = (const float*)d_in[11];
    const float* lb2 = (const float*)d_in[12];
    const float* lw3 = (const float*)d_in[13];
    const float* lb3 = (const float*)d_in[14];
    float* out = (float*)d_out;

    dim3 ggrid(2, (NN + 127) / 128);   // (n-tiles, m-tiles)
    int aggBlocks = (NN + 7) / 8;

    // order keeps gemm1 at launch index 3 so the ncu -s 5 window lands on it
    k_initprobe<<<(NN + 255) / 256, 256>>>((const int*)ei);   // 0
    k_degcnt<<<(EE + 255) / 256, 256>>>(ei, ea);              // 1
    k_pwn<<<1, 256>>>(pw);                                    // 2 (independent)
    k_gemm2<<<ggrid, 256>>>(x, 0, 0, CIN, CIN, W1);           // 3 <- ncu target
    k_scan1<<<49, 1024>>>();                                  // 4
    k_scan2<<<1, 64>>>();                                     // 5
    k_scan3<<<(NN + 255) / 256, 256>>>();                     // 6
    k_fill<<<(EE + 255) / 256, 256>>>(ei, ea);                // 7

    // layer 1 aggregate -> cat[:, 0:256]
    k_agg<<<aggBlocks, 256>>>(b1, 0, 0);
    // layer 2: xw = x1 @ W2 ; x2 -> cat[:, 256:512]
    k_gemm2<<<ggrid, 256>>>(nullptr, 1, 0, HH3, HH, W2);
    k_agg<<<aggBlocks, 256>>>(b2, HH, 0);
    // layer 3: xw = x2 @ W2 ; x3 -> cat[:, 512:768] (+ fused pooling score)
    k_gemm2<<<ggrid, 256>>>(nullptr, 1, HH, HH3, HH, W2);
    k_agg<<<aggBlocks, 256>>>(b2, 2 * HH, 1);

    // pooling
    k_rank<<<BG * RANK_BPG, 256>>>();
    k_readout1<<<384, 256>>>();
    k_readout2<<<24, 256>>>();

    // head
    k_mlp<<<BG, 256>>>(lw1, lb1, lw2, lb2, lw3, lb3, out);
}

// round 12
// speedup vs baseline: 1.0735x; 1.0735x over previous
#include <cuda_runtime.h>
#include <math.h>
#include <stdint.h>

#define NN    50000      // total nodes
#define NPG   6250       // nodes per graph
#define BG    8          // graphs
#define EE    800000     // total edges
#define CIN   512
#define HH    256
#define HH3   768
#define KSEL  5000
#define RANK_BPG 782     // ceil(6250/8) blocks per graph for rank kernel

typedef unsigned long long ull;

// ----------------------------- scratch (static device memory) ---------------
__device__ int   g_is64;
__device__ float g_deg[NN];
__device__ int   g_cnt[NN];
__device__ int   g_rowptr[NN + 1];
__device__ int   g_fill[NN];
__device__ int   g_bsum[64];
__device__ int   g_esrc[EE];
__device__ float g_enorm[EE];
__device__ float g_xw[(size_t)NN * HH];     // 51 MB
__device__ float g_cat[(size_t)NN * HH3];   // 154 MB, [x1|x2|x3]
__device__ float g_score[NN];
__device__ unsigned char g_keep[NN];
__device__ float g_pwn[HH3];
__device__ float g_psum[384 * 256];
__device__ float g_pmax[384 * 256];
__device__ float g_ro[BG * 2 * HH3];

// ----------------------------- f32x2 helpers ---------------------------------
__device__ __forceinline__ uint32_t smem_u32(const void* p) {
    uint32_t a;
    asm("{ .reg .u64 t; cvta.to.shared.u64 t, %1; cvt.u32.u64 %0, t; }" : "=r"(a) : "l"(p));
    return a;
}
__device__ __forceinline__ void ffma2(ull& d, ull a, ull b) {
    asm("fma.rn.f32x2 %0, %1, %2, %0;" : "+l"(d) : "l"(a), "l"(b));
}
__device__ __forceinline__ ull dup2(float x) {
    ull r;
    asm("mov.b64 %0, {%1, %1};" : "=l"(r) : "f"(x));
    return r;
}
__device__ __forceinline__ void lds128u64(ull& a, ull& b, uint32_t addr) {
    asm volatile("ld.shared.v2.u64 {%0,%1}, [%2];" : "=l"(a), "=l"(b) : "r"(addr));
}
__device__ __forceinline__ void unpack2(float& lo, float& hi, ull v) {
    asm("mov.b64 {%0, %1}, %2;" : "=f"(lo), "=f"(hi) : "l"(v));
}

// ----------------------------- dtype probe + init -----------------------------
__global__ void k_initprobe(const int* __restrict__ ei32) {
    int i = blockIdx.x * blockDim.x + threadIdx.x;
    if (i < NN) { g_deg[i] = 0.f; g_cnt[i] = 0; g_fill[i] = 0; }
    if (blockIdx.x == 0) {
        __shared__ int nz;
        if (threadIdx.x == 0) nz = 0;
        __syncthreads();
        int any = 0;
        for (int j = 1 + 2 * threadIdx.x; j < 4096; j += 2 * blockDim.x)
            if (ei32[j] != 0) any = 1;
        if (any) atomicAdd(&nz, 1);
        __syncthreads();
        if (threadIdx.x == 0) g_is64 = (nz == 0) ? 1 : 0;
    }
}

__device__ __forceinline__ int load_edge(const void* ei, int which, int e) {
    if (g_is64) return (int)((const long long*)ei)[(size_t)which * EE + e];
    return ((const int*)ei)[which * EE + e];
}

// ----------------------------- setup kernels --------------------------------
__global__ void k_degcnt(const void* __restrict__ ei, const float* __restrict__ ea) {
    int e = blockIdx.x * blockDim.x + threadIdx.x;
    if (e < EE) {
        int d = load_edge(ei, 1, e);
        if ((unsigned)d < NN) {
            atomicAdd(&g_deg[d], ea[e]);
            atomicAdd(&g_cnt[d], 1);
        }
    }
}

__global__ void k_scan1() {
    __shared__ int sm[1024];
    int i = blockIdx.x * 1024 + threadIdx.x;
    int v = (i < NN) ? g_cnt[i] : 0;
    sm[threadIdx.x] = v;
    __syncthreads();
    for (int off = 1; off < 1024; off <<= 1) {
        int t = (threadIdx.x >= off) ? sm[threadIdx.x - off] : 0;
        __syncthreads();
        sm[threadIdx.x] += t;
        __syncthreads();
    }
    if (i < NN) g_rowptr[i] = sm[threadIdx.x] - v;
    if (threadIdx.x == 1023) g_bsum[blockIdx.x] = sm[1023];
}

__global__ void k_scan2() {
    __shared__ int sm[64];
    int t = threadIdx.x;
    int v = (t < 49) ? g_bsum[t] : 0;
    sm[t] = v;
    __syncthreads();
    for (int off = 1; off < 64; off <<= 1) {
        int u = (t >= off) ? sm[t - off] : 0;
        __syncthreads();
        sm[t] += u;
        __syncthreads();
    }
    if (t < 49) g_bsum[t] = sm[t] - v;
}

__global__ void k_scan3() {
    int i = blockIdx.x * blockDim.x + threadIdx.x;
    if (i < NN) g_rowptr[i] += g_bsum[i >> 10];
    if (i == 0) g_rowptr[NN] = EE;
}

__global__ void k_fill(const void* __restrict__ ei, const float* __restrict__ ea) {
    int e = blockIdx.x * blockDim.x + threadIdx.x;
    if (e < EE) {
        int s = load_edge(ei, 0, e);
        int d = load_edge(ei, 1, e);
        if ((unsigned)s < NN && (unsigned)d < NN) {
            int pos = g_rowptr[d] + atomicAdd(&g_fill[d], 1);
            float ds = rsqrtf(g_deg[s] + 1.0f);
            float dd = rsqrtf(g_deg[d] + 1.0f);
            g_esrc[pos]  = s;
            g_enorm[pos] = ds * ea[e] * dd;
        }
    }
}

// ----------------------------- FFMA2 SGEMM: C = A[M,Kdim] * B[Kdim,256] ------
// CTA tile 128x128, thread tile 8 rows x (4+4 split cols), K-step 16,
// double-buffered smem. Thread (tx,ty) owns cols {tx*4..+3} and {64+tx*4..+3}
// -> B loads are contiguous 256B per 16 lanes: bank-conflict-free LDS.128.
__global__ __launch_bounds__(256, 2) void k_gemm2(
    const float* __restrict__ Aext, int use_cat, int cat_off,
    int lda, int Kdim, const float* __restrict__ B)
{
    const float* A = use_cat ? (g_cat + cat_off) : Aext;
    __shared__ __align__(16) float As[2][16][132];   // 132 pad: fewer STS conflicts
    __shared__ __align__(16) float Bs[2][16][128];
    int tid = threadIdx.x;
    int bm = blockIdx.y, bn = blockIdx.x;
    int tx = tid & 15, ty = tid >> 4;
    uint32_t bs_b = smem_u32(Bs);

    ull acc2[8][4];
    #pragma unroll
    for (int i = 0; i < 8; i++)
        #pragma unroll
        for (int j = 0; j < 4; j++) acc2[i][j] = 0ull;

    int arow0 = tid >> 2,         akq = tid & 3;      // (256+tid)&3 == tid&3
    int arow1 = (256 + tid) >> 2;
    int grow0 = bm * 128 + arow0, grow1 = bm * 128 + arow1;
    bool aok0 = grow0 < NN, aok1 = grow1 < NN;
    int bkr0 = tid >> 5,          bnc = (tid & 31) * 4;
    int bkr1 = (256 + tid) >> 5;                      // 8 + (tid>>5)

    const float* Ap0 = A + (size_t)grow0 * lda + akq * 4;
    const float* Ap1 = A + (size_t)grow1 * lda + akq * 4;
    const float* Bp0 = B + (size_t)bkr0 * HH + bn * 128 + bnc;
    const float* Bp1 = B + (size_t)bkr1 * HH + bn * 128 + bnc;

    float4 pa0, pa1, pb0, pb1;
    #define GLOAD(k0)                                                        \
        pa0 = aok0 ? *(const float4*)(Ap0 + (k0)) : make_float4(0.f,0.f,0.f,0.f); \
        pa1 = aok1 ? *(const float4*)(Ap1 + (k0)) : make_float4(0.f,0.f,0.f,0.f); \
        pb0 = *(const float4*)(Bp0 + (size_t)(k0) * HH);                     \
        pb1 = *(const float4*)(Bp1 + (size_t)(k0) * HH)
    #define SSTORE(st)                                                       \
        As[st][akq * 4 + 0][arow0] = pa0.x;                                  \
        As[st][akq * 4 + 1][arow0] = pa0.y;                                  \
        As[st][akq * 4 + 2][arow0] = pa0.z;                                  \
        As[st][akq * 4 + 3][arow0] = pa0.w;                                  \
        As[st][akq * 4 + 0][arow1] = pa1.x;                                  \
        As[st][akq * 4 + 1][arow1] = pa1.y;                                  \
        As[st][akq * 4 + 2][arow1] = pa1.z;                                  \
        As[st][akq * 4 + 3][arow1] = pa1.w;                                  \
        *(float4*)&Bs[st][bkr0][bnc] = pb0;                                  \
        *(float4*)&Bs[st][bkr1][bnc] = pb1

    GLOAD(0);
    SSTORE(0);
    __syncthreads();

    int nC = Kdim >> 4;
    for (int c = 0; c < nC; c++) {
        if (c + 1 < nC) { GLOAD((c + 1) * 16); }      // LDGs overlap FMA block
        int s = c & 1;
        uint32_t bbase = bs_b + (uint32_t)s * 8192 + (uint32_t)tx * 16;
        #pragma unroll
        for (int k = 0; k < 16; k++) {
            float ar[8];
            *(float4*)&ar[0] = *(const float4*)&As[s][k][ty * 8];
            *(float4*)&ar[4] = *(const float4*)&As[s][k][ty * 8 + 4];
            ull br2[4];
            uint32_t ba = bbase + (uint32_t)(k * 512);
            lds128u64(br2[0], br2[1], ba);            // cols tx*4..+3
            lds128u64(br2[2], br2[3], ba + 256);      // cols 64+tx*4..+3
            #pragma unroll
            for (int i = 0; i < 8; i++) {
                ull a2 = dup2(ar[i]);
                #pragma unroll
                for (int j = 0; j < 4; j++)
                    ffma2(acc2[i][j], a2, br2[j]);
            }
        }
        if (c + 1 < nC) { SSTORE((c + 1) & 1); }      // idle stage, no hazard
        __syncthreads();
    }
    #undef GLOAD
    #undef SSTORE

    #pragma unroll
    for (int i = 0; i < 8; i++) {
        int row = bm * 128 + ty * 8 + i;
        if (row < NN) {
            float c[8];
            #pragma unroll
            for (int j = 0; j < 4; j++) unpack2(c[2 * j], c[2 * j + 1], acc2[i][j]);
            float* Cp = g_xw + (size_t)row * HH + bn * 128;
            *(float4*)(Cp + tx * 4)      = make_float4(c[0], c[1], c[2], c[3]);
            *(float4*)(Cp + 64 + tx * 4) = make_float4(c[4], c[5], c[6], c[7]);
        }
    }
}

// ----------------------------- CSR gather-aggregate + bias + relu -----------
// Lane owns 8 consecutive columns (float4 x2). do_score!=0: fused TopK score.
__global__ void k_agg(const float* __restrict__ bias, int out_off, int do_score) {
    int warp = (blockIdx.x * 256 + threadIdx.x) >> 5;
    int lane = threadIdx.x & 31;
    if (warp >= NN) return;
    int n = warp;
    float di = rsqrtf(g_deg[n] + 1.0f);
    float d2 = di * di;
    const float4* xr = (const float4*)(g_xw + (size_t)n * HH);
    float4 v0 = xr[lane * 2], v1 = xr[lane * 2 + 1];
    float4 A0 = make_float4(d2 * v0.x, d2 * v0.y, d2 * v0.z, d2 * v0.w);
    float4 A1 = make_float4(d2 * v1.x, d2 * v1.y, d2 * v1.z, d2 * v1.w);

    int e0 = g_rowptr[n], e1 = g_rowptr[n + 1];
    int e = e0;
    for (; e + 1 < e1; e += 2) {
        int s0 = g_esrc[e],    s1 = g_esrc[e + 1];
        float w0 = g_enorm[e], w1 = g_enorm[e + 1];
        const float4* r0 = (const float4*)(g_xw + (size_t)s0 * HH);
        const float4* r1 = (const float4*)(g_xw + (size_t)s1 * HH);
        float4 p0 = r0[lane * 2], p1 = r0[lane * 2 + 1];
        float4 q0 = r1[lane * 2], q1 = r1[lane * 2 + 1];
        A0.x = fmaf(w0, p0.x, A0.x); A0.y = fmaf(w0, p0.y, A0.y);
        A0.z = fmaf(w0, p0.z, A0.z); A0.w = fmaf(w0, p0.w, A0.w);
        A1.x = fmaf(w0, p1.x, A1.x); A1.y = fmaf(w0, p1.y, A1.y);
        A1.z = fmaf(w0, p1.z, A1.z); A1.w = fmaf(w0, p1.w, A1.w);
        A0.x = fmaf(w1, q0.x, A0.x); A0.y = fmaf(w1, q0.y, A0.y);
        A0.z = fmaf(w1, q0.z, A0.z); A0.w = fmaf(w1, q0.w, A0.w);
        A1.x = fmaf(w1, q1.x, A1.x); A1.y = fmaf(w1, q1.y, A1.y);
        A1.z = fmaf(w1, q1.z, A1.z); A1.w = fmaf(w1, q1.w, A1.w);
    }
    if (e < e1) {
        int s = g_esrc[e];
        float w = g_enorm[e];
        const float4* r0 = (const float4*)(g_xw + (size_t)s * HH);
        float4 p0 = r0[lane * 2], p1 = r0[lane * 2 + 1];
        A0.x = fmaf(w, p0.x, A0.x); A0.y = fmaf(w, p0.y, A0.y);
        A0.z = fmaf(w, p0.z, A0.z); A0.w = fmaf(w, p0.w, A0.w);
        A1.x = fmaf(w, p1.x, A1.x); A1.y = fmaf(w, p1.y, A1.y);
        A1.z = fmaf(w, p1.z, A1.z); A1.w = fmaf(w, p1.w, A1.w);
    }
    const float4* b4 = (const float4*)bias;
    float4 B0 = b4[lane * 2], B1 = b4[lane * 2 + 1];
    A0.x = fmaxf(A0.x + B0.x, 0.f); A0.y = fmaxf(A0.y + B0.y, 0.f);
    A0.z = fmaxf(A0.z + B0.z, 0.f); A0.w = fmaxf(A0.w + B0.w, 0.f);
    A1.x = fmaxf(A1.x + B1.x, 0.f); A1.y = fmaxf(A1.y + B1.y, 0.f);
    A1.z = fmaxf(A1.z + B1.z, 0.f); A1.w = fmaxf(A1.w + B1.w, 0.f);
    float4* orow = (float4*)(g_cat + (size_t)n * HH3 + out_off);
    orow[lane * 2]     = A0;
    orow[lane * 2 + 1] = A1;

    if (do_score) {
        const float4* pw4 = (const float4*)g_pwn;
        // x3 part (cols 512..767) from registers
        float4 W0 = pw4[128 + lane * 2], W1 = pw4[128 + lane * 2 + 1];
        float s = A0.x * W0.x;
        s = fmaf(A0.y, W0.y, s); s = fmaf(A0.z, W0.z, s); s = fmaf(A0.w, W0.w, s);
        s = fmaf(A1.x, W1.x, s); s = fmaf(A1.y, W1.y, s);
        s = fmaf(A1.z, W1.z, s); s = fmaf(A1.w, W1.w, s);
        // x1,x2 parts (cols 0..511) from g_cat
        const float4* cr = (const float4*)(g_cat + (size_t)n * HH3);
        #pragma unroll
        for (int j = 0; j < 4; j++) {
            float4 cv = cr[j * 32 + lane];
            float4 pv = pw4[j * 32 + lane];
            s = fmaf(cv.x, pv.x, s); s = fmaf(cv.y, pv.y, s);
            s = fmaf(cv.z, pv.z, s); s = fmaf(cv.w, pv.w, s);
        }
        #pragma unroll
        for (int o = 16; o; o >>= 1) s += __shfl_xor_sync(0xffffffffu, s, o);
        if (lane == 0) g_score[n] = 1.f / (1.f + expf(-s));
    }
}

// ----------------------------- pooling score vector --------------------------
__global__ void k_pwn(const float* __restrict__ pw) {
    __shared__ float red[8];
    __shared__ float s_inv;
    int tid = threadIdx.x;
    float s = 0.f;
    for (int i = tid; i < HH3; i += 256) { float v = pw[i]; s += v * v; }
    #pragma unroll
    for (int o = 16; o; o >>= 1) s += __shfl_xor_sync(0xffffffffu, s, o);
    if ((tid & 31) == 0) red[tid >> 5] = s;
    __syncthreads();
    if (tid == 0) {
        float tot = 0.f;
        for (int i = 0; i < 8; i++) tot += red[i];
        s_inv = rsqrtf(tot);
    }
    __syncthreads();
    for (int i = tid; i < HH3; i += 256) g_pwn[i] = pw[i] * s_inv;
}

// exact top-K selection via rank counting (matches jax top_k tie semantics)
__global__ void k_rank() {
    __shared__ float ss[NPG];
    int g  = blockIdx.x / RANK_BPG;
    int bb = blockIdx.x % RANK_BPG;
    for (int i = threadIdx.x; i < NPG; i += 256) ss[i] = g_score[g * NPG + i];
    __syncthreads();
    int wi = threadIdx.x >> 5, lane = threadIdx.x & 31;
    int i = bb * 8 + wi;
    if (i >= NPG) return;
    float si = ss[i];
    int cnt = 0;
    for (int j0 = 0; j0 < NPG; j0 += 32) {
        int j = j0 + lane;
        bool p = false;
        if (j < NPG) {
            float sj = ss[j];
            p = (sj > si) || (sj == si && j < i);
        }
        cnt += __popc(__ballot_sync(0xffffffffu, p));
    }
    if (lane == 0) g_keep[g * NPG + i] = (cnt < KSEL) ? 1 : 0;
}

// ----------------------------- readout (mean + max over selected) -----------
__global__ void k_readout1() {
    int b  = blockIdx.x;        // b = g*48 + cb*16 + ch
    int g  = b / 48;
    int cb = (b / 16) % 3;
    int ch = b % 16;
    int col = cb * 256 + threadIdx.x;
    int i0 = ch * 391, i1 = min(NPG, i0 + 391);
    float sum = 0.f, mx = -3.402823e38f;
    for (int i = i0; i < i1; i++) {
        int n = g * NPG + i;
        if (g_keep[n]) {
            float s = g_score[n];
            float v = s * g_cat[(size_t)n * HH3 + col];
            sum += v;
            mx = fmaxf(mx, v);
        }
    }
    g_psum[b * 256 + threadIdx.x] = sum;
    g_pmax[b * 256 + threadIdx.x] = mx;
}

__global__ void k_readout2() {
    int b = blockIdx.x;
    int g = b / 3, cb = b % 3;
    int col = cb * 256 + threadIdx.x;
    float sum = 0.f, mx = -3.402823e38f;
    for (int ch = 0; ch < 16; ch++) {
        int idx = ((g * 3 + cb) * 16 + ch) * 256 + threadIdx.x;
        sum += g_psum[idx];
        mx = fmaxf(mx, g_pmax[idx]);
    }
    g_ro[g * 2 * HH3 + col]       = sum * (1.0f / KSEL);
    g_ro[g * 2 * HH3 + HH3 + col] = mx;
}

// ----------------------------- MLP head -------------------------------------
__global__ void k_mlp(const float* __restrict__ lw1, const float* __restrict__ lb1,
                      const float* __restrict__ lw2, const float* __restrict__ lb2,
                      const float* __restrict__ lw3, const float* __restrict__ lb3,
                      float* __restrict__ out) {
    __shared__ float ro[2 * HH3];
    __shared__ float h1[HH];
    __shared__ float h2[HH / 2];
    int g = blockIdx.x, tid = threadIdx.x;
    for (int i = tid; i < 2 * HH3; i += 256) ro[i] = g_ro[g * 2 * HH3 + i];
    __syncthreads();
    float a0 = 0.f, a1 = 0.f, a2 = 0.f, a3 = 0.f;
    for (int k = 0; k < 2 * HH3; k += 4) {
        a0 = fmaf(ro[k + 0], lw1[(k + 0) * HH + tid], a0);
        a1 = fmaf(ro[k + 1], lw1[(k + 1) * HH + tid], a1);
        a2 = fmaf(ro[k + 2], lw1[(k + 2) * HH + tid], a2);
        a3 = fmaf(ro[k + 3], lw1[(k + 3) * HH + tid], a3);
    }
    h1[tid] = fmaxf(a0 + a1 + a2 + a3 + lb1[tid], 0.f);
    __syncthreads();
    if (tid < HH / 2) {
        float b0 = 0.f, b1v = 0.f;
        for (int k = 0; k < HH; k += 2) {
            b0  = fmaf(h1[k],     lw2[k * (HH / 2) + tid],       b0);
            b1v = fmaf(h1[k + 1], lw2[(k + 1) * (HH / 2) + tid], b1v);
        }
        h2[tid] = fmaxf(b0 + b1v + lb2[tid], 0.f);
    }
    __syncthreads();
    if (tid < 3) {
        float s = lb3[tid];
        for (int k = 0; k < HH / 2; k++) s = fmaf(h2[k], lw3[k * 3 + tid], s);
        out[g * 3 + tid] = s;
    }
}

// ----------------------------- launch ---------------------------------------
extern "C" void kernel_launch(void* const* d_in, const int* in_sizes, int n_in,
                              void* d_out, int out_size) {
    const float* x   = (const float*)d_in[0];
    const void*  ei  = d_in[1];              // int32 or int64 (probed at runtime)
    const float* ea  = (const float*)d_in[2];
    // d_in[3] = batch (unused): graph id = node / NPG
    const float* W1  = (const float*)d_in[4];
    const float* b1  = (const float*)d_in[5];
    const float* W2  = (const float*)d_in[6];
    const float* b2  = (const float*)d_in[7];
    const float* pw  = (const float*)d_in[8];
    const float* lw1 = (const float*)d_in[9];
    const float* lb1 = (const float*)d_in[10];
    const float* lw2 = (const float*)d_in[11];
    const float* lb2 = (const float*)d_in[12];
    const float* lw3 = (const float*)d_in[13];
    const float* lb3 = (const float*)d_in[14];
    float* out = (float*)d_out;

    dim3 ggrid(2, (NN + 127) / 128);   // (n-tiles, m-tiles)
    int aggBlocks = (NN + 7) / 8;

    // order keeps gemm1 at launch index 3 so the ncu -s 5 window lands on it
    k_initprobe<<<(NN + 255) / 256, 256>>>((const int*)ei);   // 0
    k_degcnt<<<(EE + 255) / 256, 256>>>(ei, ea);              // 1
    k_pwn<<<1, 256>>>(pw);                                    // 2 (independent)
    k_gemm2<<<ggrid, 256>>>(x, 0, 0, CIN, CIN, W1);           // 3 <- ncu target
    k_scan1<<<49, 1024>>>();                                  // 4
    k_scan2<<<1, 64>>>();                                     // 5
    k_scan3<<<(NN + 255) / 256, 256>>>();                     // 6
    k_fill<<<(EE + 255) / 256, 256>>>(ei, ea);                // 7

    // layer 1 aggregate -> cat[:, 0:256]
    k_agg<<<aggBlocks, 256>>>(b1, 0, 0);
    // layer 2: xw = x1 @ W2 ; x2 -> cat[:, 256:512]
    k_gemm2<<<ggrid, 256>>>(nullptr, 1, 0, HH3, HH, W2);
    k_agg<<<aggBlocks, 256>>>(b2, HH, 0);
    // layer 3: xw = x2 @ W2 ; x3 -> cat[:, 512:768] (+ fused pooling score)
    k_gemm2<<<ggrid, 256>>>(nullptr, 1, HH, HH3, HH, W2);
    k_agg<<<aggBlocks, 256>>>(b2, 2 * HH, 1);

    // pooling
    k_rank<<<BG * RANK_BPG, 256>>>();
    k_readout1<<<384, 256>>>();
    k_readout2<<<24, 256>>>();

    // head
    k_mlp<<<BG, 256>>>(lw1, lb1, lw2, lb2, lw3, lb3, out);
}

// round 14
// speedup vs baseline: 1.0853x; 1.0109x over previous
#include <cuda_runtime.h>
#include <math.h>
#include <stdint.h>

#define NN    50000      // total nodes
#define NPG   6250       // nodes per graph
#define BG    8          // graphs
#define EE    800000     // total edges
#define CIN   512
#define HH    256
#define HH3   768
#define KSEL  5000
#define RANK_BPG 782     // ceil(6250/8) blocks per graph for rank kernel

typedef unsigned long long ull;

// ----------------------------- scratch (static device memory) ---------------
__device__ int   g_is64;
__device__ float g_deg[NN];
__device__ int   g_cnt[NN];
__device__ int   g_rowptr[NN + 1];
__device__ int   g_fill[NN];
__device__ int   g_bsum[64];
__device__ int   g_esrc[EE];
__device__ float g_enorm[EE];
__device__ float g_xw[(size_t)NN * HH];     // 51 MB
__device__ float g_cat[(size_t)NN * HH3];   // 154 MB, [x1|x2|x3]
__device__ float g_score[NN];
__device__ unsigned char g_keep[NN];
__device__ float g_pwn[HH3];
__device__ float g_psum[384 * 256];
__device__ float g_pmax[384 * 256];
__device__ float g_ro[BG * 2 * HH3];

// ----------------------------- f32x2 helpers ---------------------------------
__device__ __forceinline__ uint32_t smem_u32(const void* p) {
    uint32_t a;
    asm("{ .reg .u64 t; cvta.to.shared.u64 t, %1; cvt.u32.u64 %0, t; }" : "=r"(a) : "l"(p));
    return a;
}
__device__ __forceinline__ void ffma2(ull& d, ull a, ull b) {
    asm("fma.rn.f32x2 %0, %1, %2, %0;" : "+l"(d) : "l"(a), "l"(b));
}
__device__ __forceinline__ ull dup2(float x) {
    ull r;
    asm("mov.b64 %0, {%1, %1};" : "=l"(r) : "f"(x));
    return r;
}
__device__ __forceinline__ void lds128u64(ull& a, ull& b, uint32_t addr) {
    asm volatile("ld.shared.v2.u64 {%0,%1}, [%2];" : "=l"(a), "=l"(b) : "r"(addr));
}
__device__ __forceinline__ void unpack2(float& lo, float& hi, ull v) {
    asm("mov.b64 {%0, %1}, %2;" : "=f"(lo), "=f"(hi) : "l"(v));
}
// edge FMA accumulate (function, not macro: avoids token-capture of ".w")
__device__ __forceinline__ void edge_fma(float4& A0, float4& A1, float wgt,
                                         const float4& p0, const float4& p1) {
    A0.x = fmaf(wgt, p0.x, A0.x); A0.y = fmaf(wgt, p0.y, A0.y);
    A0.z = fmaf(wgt, p0.z, A0.z); A0.w = fmaf(wgt, p0.w, A0.w);
    A1.x = fmaf(wgt, p1.x, A1.x); A1.y = fmaf(wgt, p1.y, A1.y);
    A1.z = fmaf(wgt, p1.z, A1.z); A1.w = fmaf(wgt, p1.w, A1.w);
}

// ----------------------------- dtype probe + init -----------------------------
__global__ void k_initprobe(const int* __restrict__ ei32) {
    int i = blockIdx.x * blockDim.x + threadIdx.x;
    if (i < NN) { g_deg[i] = 0.f; g_cnt[i] = 0; g_fill[i] = 0; }
    if (blockIdx.x == 0) {
        __shared__ int nz;
        if (threadIdx.x == 0) nz = 0;
        __syncthreads();
        int any = 0;
        for (int j = 1 + 2 * threadIdx.x; j < 4096; j += 2 * blockDim.x)
            if (ei32[j] != 0) any = 1;
        if (any) atomicAdd(&nz, 1);
        __syncthreads();
        if (threadIdx.x == 0) g_is64 = (nz == 0) ? 1 : 0;
    }
}

__device__ __forceinline__ int load_edge(const void* ei, int which, int e) {
    if (g_is64) return (int)((const long long*)ei)[(size_t)which * EE + e];
    return ((const int*)ei)[which * EE + e];
}

// ----------------------------- setup kernels --------------------------------
__global__ void k_degcnt(const void* __restrict__ ei, const float* __restrict__ ea) {
    int e = blockIdx.x * blockDim.x + threadIdx.x;
    if (e < EE) {
        int d = load_edge(ei, 1, e);
        if ((unsigned)d < NN) {
            atomicAdd(&g_deg[d], ea[e]);
            atomicAdd(&g_cnt[d], 1);
        }
    }
}

__global__ void k_scan1() {
    __shared__ int sm[1024];
    int i = blockIdx.x * 1024 + threadIdx.x;
    int v = (i < NN) ? g_cnt[i] : 0;
    sm[threadIdx.x] = v;
    __syncthreads();
    for (int off = 1; off < 1024; off <<= 1) {
        int t = (threadIdx.x >= off) ? sm[threadIdx.x - off] : 0;
        __syncthreads();
        sm[threadIdx.x] += t;
        __syncthreads();
    }
    if (i < NN) g_rowptr[i] = sm[threadIdx.x] - v;
    if (threadIdx.x == 1023) g_bsum[blockIdx.x] = sm[1023];
}

__global__ void k_scan2() {
    __shared__ int sm[64];
    int t = threadIdx.x;
    int v = (t < 49) ? g_bsum[t] : 0;
    sm[t] = v;
    __syncthreads();
    for (int off = 1; off < 64; off <<= 1) {
        int u = (t >= off) ? sm[t - off] : 0;
        __syncthreads();
        sm[t] += u;
        __syncthreads();
    }
    if (t < 49) g_bsum[t] = sm[t] - v;
}

__global__ void k_scan3() {
    int i = blockIdx.x * blockDim.x + threadIdx.x;
    if (i < NN) g_rowptr[i] += g_bsum[i >> 10];
    if (i == 0) g_rowptr[NN] = EE;
}

__global__ void k_fill(const void* __restrict__ ei, const float* __restrict__ ea) {
    int e = blockIdx.x * blockDim.x + threadIdx.x;
    if (e < EE) {
        int s = load_edge(ei, 0, e);
        int d = load_edge(ei, 1, e);
        if ((unsigned)s < NN && (unsigned)d < NN) {
            int pos = g_rowptr[d] + atomicAdd(&g_fill[d], 1);
            float ds = rsqrtf(g_deg[s] + 1.0f);
            float dd = rsqrtf(g_deg[d] + 1.0f);
            g_esrc[pos]  = s;
            g_enorm[pos] = ds * ea[e] * dd;
        }
    }
}

// ----------------------------- FFMA2 SGEMM: C = A[M,Kdim] * B[Kdim,256] ------
// CTA tile 128x64, thread tile 8 rows x 4 cols, K-step 16, double-buffered.
// Small acc (16 ull regs) -> ~80 regs -> 3 CTAs/SM (24 warps) for latency hiding.
__global__ __launch_bounds__(256, 3) void k_gemm2(
    const float* __restrict__ Aext, int use_cat, int cat_off,
    int lda, int Kdim, const float* __restrict__ B)
{
    const float* A = use_cat ? (g_cat + cat_off) : Aext;
    __shared__ __align__(16) float As[2][16][132];   // 132 pad vs STS conflicts
    __shared__ __align__(16) float Bs[2][16][64];
    int tid = threadIdx.x;
    int bm = blockIdx.y, bn = blockIdx.x;
    int tx = tid & 15, ty = tid >> 4;   // tx: col group (4 cols), ty: row group (8 rows)
    uint32_t bs_b = smem_u32(Bs);

    ull acc2[8][2];
    #pragma unroll
    for (int i = 0; i < 8; i++) { acc2[i][0] = 0ull; acc2[i][1] = 0ull; }

    // A tile loads: 512 float4 items; item i: row=i>>2, kq=i&3
    int arow0 = tid >> 2,         akq = tid & 3;
    int arow1 = (256 + tid) >> 2;
    int grow0 = bm * 128 + arow0, grow1 = bm * 128 + arow1;
    bool aok0 = grow0 < NN, aok1 = grow1 < NN;
    // B tile loads: 256 float4 items; item tid: krow=tid>>4, nc=(tid&15)*4
    int bkr = tid >> 4, bnc = (tid & 15) * 4;

    const float* Ap0 = A + (size_t)grow0 * lda + akq * 4;
    const float* Ap1 = A + (size_t)grow1 * lda + akq * 4;
    const float* Bp  = B + (size_t)bkr * HH + bn * 64 + bnc;

    float4 pa0, pa1, pb;
    #define GLOAD(k0)                                                        \
        pa0 = aok0 ? *(const float4*)(Ap0 + (k0)) : make_float4(0.f,0.f,0.f,0.f); \
        pa1 = aok1 ? *(const float4*)(Ap1 + (k0)) : make_float4(0.f,0.f,0.f,0.f); \
        pb  = *(const float4*)(Bp + (size_t)(k0) * HH)
    #define SSTORE(st)                                                       \
        As[st][akq * 4 + 0][arow0] = pa0.x;                                  \
        As[st][akq * 4 + 1][arow0] = pa0.y;                                  \
        As[st][akq * 4 + 2][arow0] = pa0.z;                                  \
        As[st][akq * 4 + 3][arow0] = pa0.w;                                  \
        As[st][akq * 4 + 0][arow1] = pa1.x;                                  \
        As[st][akq * 4 + 1][arow1] = pa1.y;                                  \
        As[st][akq * 4 + 2][arow1] = pa1.z;                                  \
        As[st][akq * 4 + 3][arow1] = pa1.w;                                  \
        *(float4*)&Bs[st][bkr][bnc] = pb

    GLOAD(0);
    SSTORE(0);
    __syncthreads();

    int nC = Kdim >> 4;
    for (int c = 0; c < nC; c++) {
        if (c + 1 < nC) { GLOAD((c + 1) * 16); }      // LDGs overlap FMA block
        int s = c & 1;
        uint32_t bbase = bs_b + (uint32_t)s * 4096 + (uint32_t)tx * 16;
        #pragma unroll
        for (int k = 0; k < 16; k++) {
            float ar[8];
            *(float4*)&ar[0] = *(const float4*)&As[s][k][ty * 8];
            *(float4*)&ar[4] = *(const float4*)&As[s][k][ty * 8 + 4];
            ull br0, br1;
            lds128u64(br0, br1, bbase + (uint32_t)(k * 256));  // cols tx*4..+3
            #pragma unroll
            for (int i = 0; i < 8; i++) {
                ull a2 = dup2(ar[i]);
                ffma2(acc2[i][0], a2, br0);
                ffma2(acc2[i][1], a2, br1);
            }
        }
        if (c + 1 < nC) { SSTORE((c + 1) & 1); }
        __syncthreads();
    }
    #undef GLOAD
    #undef SSTORE

    #pragma unroll
    for (int i = 0; i < 8; i++) {
        int row = bm * 128 + ty * 8 + i;
        if (row < NN) {
            float c0, c1, c2, c3;
            unpack2(c0, c1, acc2[i][0]);
            unpack2(c2, c3, acc2[i][1]);
            *(float4*)(g_xw + (size_t)row * HH + bn * 64 + tx * 4) =
                make_float4(c0, c1, c2, c3);
        }
    }
}

// ----------------------------- CSR gather-aggregate + bias + relu -----------
// Lane owns 8 consecutive columns (float4 x2); edge loop unrolled x4 for MLP.
__global__ void k_agg(const float* __restrict__ bias, int out_off, int do_score) {
    int warp = (blockIdx.x * 256 + threadIdx.x) >> 5;
    int lane = threadIdx.x & 31;
    if (warp >= NN) return;
    int n = warp;
    float di = rsqrtf(g_deg[n] + 1.0f);
    float d2 = di * di;
    const float4* xr = (const float4*)(g_xw + (size_t)n * HH);
    float4 v0 = xr[lane * 2], v1 = xr[lane * 2 + 1];
    float4 A0 = make_float4(d2 * v0.x, d2 * v0.y, d2 * v0.z, d2 * v0.w);
    float4 A1 = make_float4(d2 * v1.x, d2 * v1.y, d2 * v1.z, d2 * v1.w);

    int e0 = g_rowptr[n], e1 = g_rowptr[n + 1];
    int e = e0;
    for (; e + 3 < e1; e += 4) {
        int s0 = g_esrc[e],     s1 = g_esrc[e + 1];
        int s2 = g_esrc[e + 2], s3 = g_esrc[e + 3];
        float w0 = g_enorm[e],     w1 = g_enorm[e + 1];
        float w2 = g_enorm[e + 2], w3 = g_enorm[e + 3];
        const float4* r0 = (const float4*)(g_xw + (size_t)s0 * HH);
        const float4* r1 = (const float4*)(g_xw + (size_t)s1 * HH);
        const float4* r2 = (const float4*)(g_xw + (size_t)s2 * HH);
        const float4* r3 = (const float4*)(g_xw + (size_t)s3 * HH);
        float4 p00 = r0[lane * 2], p01 = r0[lane * 2 + 1];
        float4 p10 = r1[lane * 2], p11 = r1[lane * 2 + 1];
        float4 p20 = r2[lane * 2], p21 = r2[lane * 2 + 1];
        float4 p30 = r3[lane * 2], p31 = r3[lane * 2 + 1];
        edge_fma(A0, A1, w0, p00, p01);
        edge_fma(A0, A1, w1, p10, p11);
        edge_fma(A0, A1, w2, p20, p21);
        edge_fma(A0, A1, w3, p30, p31);
    }
    for (; e < e1; e++) {
        int s = g_esrc[e];
        float wgt = g_enorm[e];
        const float4* r0 = (const float4*)(g_xw + (size_t)s * HH);
        float4 p0 = r0[lane * 2], p1 = r0[lane * 2 + 1];
        edge_fma(A0, A1, wgt, p0, p1);
    }
    const float4* b4 = (const float4*)bias;
    float4 B0 = b4[lane * 2], B1 = b4[lane * 2 + 1];
    A0.x = fmaxf(A0.x + B0.x, 0.f); A0.y = fmaxf(A0.y + B0.y, 0.f);
    A0.z = fmaxf(A0.z + B0.z, 0.f); A0.w = fmaxf(A0.w + B0.w, 0.f);
    A1.x = fmaxf(A1.x + B1.x, 0.f); A1.y = fmaxf(A1.y + B1.y, 0.f);
    A1.z = fmaxf(A1.z + B1.z, 0.f); A1.w = fmaxf(A1.w + B1.w, 0.f);
    float4* orow = (float4*)(g_cat + (size_t)n * HH3 + out_off);
    orow[lane * 2]     = A0;
    orow[lane * 2 + 1] = A1;

    if (do_score) {
        const float4* pw4 = (const float4*)g_pwn;
        float4 W0 = pw4[128 + lane * 2], W1 = pw4[128 + lane * 2 + 1];
        float s = A0.x * W0.x;
        s = fmaf(A0.y, W0.y, s); s = fmaf(A0.z, W0.z, s); s = fmaf(A0.w, W0.w, s);
        s = fmaf(A1.x, W1.x, s); s = fmaf(A1.y, W1.y, s);
        s = fmaf(A1.z, W1.z, s); s = fmaf(A1.w, W1.w, s);
        const float4* cr = (const float4*)(g_cat + (size_t)n * HH3);
        #pragma unroll
        for (int j = 0; j < 4; j++) {
            float4 cv = cr[j * 32 + lane];
            float4 pv = pw4[j * 32 + lane];
            s = fmaf(cv.x, pv.x, s); s = fmaf(cv.y, pv.y, s);
            s = fmaf(cv.z, pv.z, s); s = fmaf(cv.w, pv.w, s);
        }
        #pragma unroll
        for (int o = 16; o; o >>= 1) s += __shfl_xor_sync(0xffffffffu, s, o);
        if (lane == 0) g_score[n] = 1.f / (1.f + expf(-s));
    }
}

// ----------------------------- pooling score vector --------------------------
__global__ void k_pwn(const float* __restrict__ pw) {
    __shared__ float red[8];
    __shared__ float s_inv;
    int tid = threadIdx.x;
    float s = 0.f;
    for (int i = tid; i < HH3; i += 256) { float v = pw[i]; s += v * v; }
    #pragma unroll
    for (int o = 16; o; o >>= 1) s += __shfl_xor_sync(0xffffffffu, s, o);
    if ((tid & 31) == 0) red[tid >> 5] = s;
    __syncthreads();
    if (tid == 0) {
        float tot = 0.f;
        for (int i = 0; i < 8; i++) tot += red[i];
        s_inv = rsqrtf(tot);
    }
    __syncthreads();
    for (int i = tid; i < HH3; i += 256) g_pwn[i] = pw[i] * s_inv;
}

// exact top-K selection via rank counting (matches jax top_k tie semantics)
__global__ void k_rank() {
    __shared__ float ss[NPG];
    int g  = blockIdx.x / RANK_BPG;
    int bb = blockIdx.x % RANK_BPG;
    for (int i = threadIdx.x; i < NPG; i += 256) ss[i] = g_score[g * NPG + i];
    __syncthreads();
    int wi = threadIdx.x >> 5, lane = threadIdx.x & 31;
    int i = bb * 8 + wi;
    if (i >= NPG) return;
    float si = ss[i];
    int cnt = 0;
    for (int j0 = 0; j0 < NPG; j0 += 32) {
        int j = j0 + lane;
        bool p = false;
        if (j < NPG) {
            float sj = ss[j];
            p = (sj > si) || (sj == si && j < i);
        }
        cnt += __popc(__ballot_sync(0xffffffffu, p));
    }
    if (lane == 0) g_keep[g * NPG + i] = (cnt < KSEL) ? 1 : 0;
}

// ----------------------------- readout (mean + max over selected) -----------
__global__ void k_readout1() {
    int b  = blockIdx.x;        // b = g*48 + cb*16 + ch
    int g  = b / 48;
    int cb = (b / 16) % 3;
    int ch = b % 16;
    int col = cb * 256 + threadIdx.x;
    int i0 = ch * 391, i1 = min(NPG, i0 + 391);
    float sum = 0.f, mx = -3.402823e38f;
    for (int i = i0; i < i1; i++) {
        int n = g * NPG + i;
        if (g_keep[n]) {
            float s = g_score[n];
            float v = s * g_cat[(size_t)n * HH3 + col];
            sum += v;
            mx = fmaxf(mx, v);
        }
    }
    g_psum[b * 256 + threadIdx.x] = sum;
    g_pmax[b * 256 + threadIdx.x] = mx;
}

__global__ void k_readout2() {
    int b = blockIdx.x;
    int g = b / 3, cb = b % 3;
    int col = cb * 256 + threadIdx.x;
    float sum = 0.f, mx = -3.402823e38f;
    for (int ch = 0; ch < 16; ch++) {
        int idx = ((g * 3 + cb) * 16 + ch) * 256 + threadIdx.x;
        sum += g_psum[idx];
        mx = fmaxf(mx, g_pmax[idx]);
    }
    g_ro[g * 2 * HH3 + col]       = sum * (1.0f / KSEL);
    g_ro[g * 2 * HH3 + HH3 + col] = mx;
}

// ----------------------------- MLP head -------------------------------------
__global__ void k_mlp(const float* __restrict__ lw1, const float* __restrict__ lb1,
                      const float* __restrict__ lw2, const float* __restrict__ lb2,
                      const float* __restrict__ lw3, const float* __restrict__ lb3,
                      float* __restrict__ out) {
    __shared__ float ro[2 * HH3];
    __shared__ float h1[HH];
    __shared__ float h2[HH / 2];
    int g = blockIdx.x, tid = threadIdx.x;
    for (int i = tid; i < 2 * HH3; i += 256) ro[i] = g_ro[g * 2 * HH3 + i];
    __syncthreads();
    float a0 = 0.f, a1 = 0.f, a2 = 0.f, a3 = 0.f;
    for (int k = 0; k < 2 * HH3; k += 4) {
        a0 = fmaf(ro[k + 0], lw1[(k + 0) * HH + tid], a0);
        a1 = fmaf(ro[k + 1], lw1[(k + 1) * HH + tid], a1);
        a2 = fmaf(ro[k + 2], lw1[(k + 2) * HH + tid], a2);
        a3 = fmaf(ro[k + 3], lw1[(k + 3) * HH + tid], a3);
    }
    h1[tid] = fmaxf(a0 + a1 + a2 + a3 + lb1[tid], 0.f);
    __syncthreads();
    if (tid < HH / 2) {
        float b0 = 0.f, b1v = 0.f;
        for (int k = 0; k < HH; k += 2) {
            b0  = fmaf(h1[k],     lw2[k * (HH / 2) + tid],       b0);
            b1v = fmaf(h1[k + 1], lw2[(k + 1) * (HH / 2) + tid], b1v);
        }
        h2[tid] = fmaxf(b0 + b1v + lb2[tid], 0.f);
    }
    __syncthreads();
    if (tid < 3) {
        float s = lb3[tid];
        for (int k = 0; k < HH / 2; k++) s = fmaf(h2[k], lw3[k * 3 + tid], s);
        out[g * 3 + tid] = s;
    }
}

// ----------------------------- launch ---------------------------------------
extern "C" void kernel_launch(void* const* d_in, const int* in_sizes, int n_in,
                              void* d_out, int out_size) {
    const float* x   = (const float*)d_in[0];
    const void*  ei  = d_in[1];              // int32 or int64 (probed at runtime)
    const float* ea  = (const float*)d_in[2];
    // d_in[3] = batch (unused): graph id = node / NPG
    const float* W1  = (const float*)d_in[4];
    const float* b1  = (const float*)d_in[5];
    const float* W2  = (const float*)d_in[6];
    const float* b2  = (const float*)d_in[7];
    const float* pw  = (const float*)d_in[8];
    const float* lw1 = (const float*)d_in[9];
    const float* lb1 = (const float*)d_in[10];
    const float* lw2 = (const float*)d_in[11];
    const float* lb2 = (const float*)d_in[12];
    const float* lw3 = (const float*)d_in[13];
    const float* lb3 = (const float*)d_in[14];
    float* out = (float*)d_out;

    dim3 ggrid(4, (NN + 127) / 128);   // (n-tiles of 64, m-tiles of 128)
    int aggBlocks = (NN + 7) / 8;

    // order keeps gemm1 at launch index 3 so the ncu -s 5 window lands on it
    k_initprobe<<<(NN + 255) / 256, 256>>>((const int*)ei);   // 0
    k_degcnt<<<(EE + 255) / 256, 256>>>(ei, ea);              // 1
    k_pwn<<<1, 256>>>(pw);                                    // 2 (independent)
    k_gemm2<<<ggrid, 256>>>(x, 0, 0, CIN, CIN, W1);           // 3 <- ncu target
    k_scan1<<<49, 1024>>>();                                  // 4
    k_scan2<<<1, 64>>>();                                     // 5
    k_scan3<<<(NN + 255) / 256, 256>>>();                     // 6
    k_fill<<<(EE + 255) / 256, 256>>>(ei, ea);                // 7

    // layer 1 aggregate -> cat[:, 0:256]
    k_agg<<<aggBlocks, 256>>>(b1, 0, 0);
    // layer 2: xw = x1 @ W2 ; x2 -> cat[:, 256:512]
    k_gemm2<<<ggrid, 256>>>(nullptr, 1, 0, HH3, HH, W2);
    k_agg<<<aggBlocks, 256>>>(b2, HH, 0);
    // layer 3: xw = x2 @ W2 ; x3 -> cat[:, 512:768] (+ fused pooling score)
    k_gemm2<<<ggrid, 256>>>(nullptr, 1, HH, HH3, HH, W2);
    k_agg<<<aggBlocks, 256>>>(b2, 2 * HH, 1);

    // pooling
    k_rank<<<BG * RANK_BPG, 256>>>();
    k_readout1<<<384, 256>>>();
    k_readout2<<<24, 256>>>();

    // head
    k_mlp<<<BG, 256>>>(lw1, lb1, lw2, lb2, lw3, lb3, out);
}

// round 15
// speedup vs baseline: 1.0979x; 1.0117x over previous
#include <cuda_runtime.h>
#include <math.h>
#include <stdint.h>

#define NN    50000      // total nodes
#define NPG   6250       // nodes per graph
#define BG    8          // graphs
#define EE    800000     // total edges
#define CIN   512
#define HH    256
#define HH3   768
#define KSEL  5000
#define RANK_BPG 782     // ceil(6250/8) blocks per graph for rank kernel

typedef unsigned long long ull;

// ----------------------------- scratch (static device memory) ---------------
__device__ int   g_is64;
__device__ float g_deg[NN];
__device__ int   g_cnt[NN];
__device__ int   g_rowptr[NN + 1];
__device__ int   g_fill[NN];
__device__ int   g_bsum[64];
__device__ int   g_esrc[EE];
__device__ float g_enorm[EE];
__device__ float g_xw[(size_t)NN * HH];     // 51 MB
__device__ float g_cat[(size_t)NN * HH3];   // 154 MB, [x1|x2|x3]
__device__ float g_score[NN];
__device__ unsigned char g_keep[NN];
__device__ float g_pwn[HH3];
__device__ float g_psum[384 * 256];
__device__ float g_pmax[384 * 256];
__device__ float g_ro[BG * 2 * HH3];

// ----------------------------- f32x2 helpers ---------------------------------
__device__ __forceinline__ uint32_t smem_u32(const void* p) {
    uint32_t a;
    asm("{ .reg .u64 t; cvta.to.shared.u64 t, %1; cvt.u32.u64 %0, t; }" : "=r"(a) : "l"(p));
    return a;
}
__device__ __forceinline__ void ffma2(ull& d, ull a, ull b) {
    asm("fma.rn.f32x2 %0, %1, %2, %0;" : "+l"(d) : "l"(a), "l"(b));
}
__device__ __forceinline__ ull dup2(float x) {
    ull r;
    asm("mov.b64 %0, {%1, %1};" : "=l"(r) : "f"(x));
    return r;
}
__device__ __forceinline__ void lds128u64(ull& a, ull& b, uint32_t addr) {
    asm volatile("ld.shared.v2.u64 {%0,%1}, [%2];" : "=l"(a), "=l"(b) : "r"(addr));
}
__device__ __forceinline__ void unpack2(float& lo, float& hi, ull v) {
    asm("mov.b64 {%0, %1}, %2;" : "=f"(lo), "=f"(hi) : "l"(v));
}
// edge FMA accumulate (function, not macro: avoids token-capture of ".w")
__device__ __forceinline__ void edge_fma(float4& A0, float4& A1, float wgt,
                                         const float4& p0, const float4& p1) {
    A0.x = fmaf(wgt, p0.x, A0.x); A0.y = fmaf(wgt, p0.y, A0.y);
    A0.z = fmaf(wgt, p0.z, A0.z); A0.w = fmaf(wgt, p0.w, A0.w);
    A1.x = fmaf(wgt, p1.x, A1.x); A1.y = fmaf(wgt, p1.y, A1.y);
    A1.z = fmaf(wgt, p1.z, A1.z); A1.w = fmaf(wgt, p1.w, A1.w);
}

// ----------------------------- dtype probe + init -----------------------------
__global__ void k_initprobe(const int* __restrict__ ei32) {
    int i = blockIdx.x * blockDim.x + threadIdx.x;
    if (i < NN) { g_deg[i] = 0.f; g_cnt[i] = 0; g_fill[i] = 0; }
    if (blockIdx.x == 0) {
        __shared__ int nz;
        if (threadIdx.x == 0) nz = 0;
        __syncthreads();
        int any = 0;
        for (int j = 1 + 2 * threadIdx.x; j < 4096; j += 2 * blockDim.x)
            if (ei32[j] != 0) any = 1;
        if (any) atomicAdd(&nz, 1);
        __syncthreads();
        if (threadIdx.x == 0) g_is64 = (nz == 0) ? 1 : 0;
    }
}

__device__ __forceinline__ int load_edge(const void* ei, int which, int e) {
    if (g_is64) return (int)((const long long*)ei)[(size_t)which * EE + e];
    return ((const int*)ei)[which * EE + e];
}

// ----------------------------- setup kernels --------------------------------
__global__ void k_degcnt(const void* __restrict__ ei, const float* __restrict__ ea) {
    int e = blockIdx.x * blockDim.x + threadIdx.x;
    if (e < EE) {
        int d = load_edge(ei, 1, e);
        if ((unsigned)d < NN) {
            atomicAdd(&g_deg[d], ea[e]);
            atomicAdd(&g_cnt[d], 1);
        }
    }
}

__global__ void k_scan1() {
    __shared__ int sm[1024];
    int i = blockIdx.x * 1024 + threadIdx.x;
    int v = (i < NN) ? g_cnt[i] : 0;
    sm[threadIdx.x] = v;
    __syncthreads();
    for (int off = 1; off < 1024; off <<= 1) {
        int t = (threadIdx.x >= off) ? sm[threadIdx.x - off] : 0;
        __syncthreads();
        sm[threadIdx.x] += t;
        __syncthreads();
    }
    if (i < NN) g_rowptr[i] = sm[threadIdx.x] - v;
    if (threadIdx.x == 1023) g_bsum[blockIdx.x] = sm[1023];
}

__global__ void k_scan2() {
    __shared__ int sm[64];
    int t = threadIdx.x;
    int v = (t < 49) ? g_bsum[t] : 0;
    sm[t] = v;
    __syncthreads();
    for (int off = 1; off < 64; off <<= 1) {
        int u = (t >= off) ? sm[t - off] : 0;
        __syncthreads();
        sm[t] += u;
        __syncthreads();
    }
    if (t < 49) g_bsum[t] = sm[t] - v;
}

__global__ void k_scan3() {
    int i = blockIdx.x * blockDim.x + threadIdx.x;
    if (i < NN) g_rowptr[i] += g_bsum[i >> 10];
    if (i == 0) g_rowptr[NN] = EE;
}

__global__ void k_fill(const void* __restrict__ ei, const float* __restrict__ ea) {
    int e = blockIdx.x * blockDim.x + threadIdx.x;
    if (e < EE) {
        int s = load_edge(ei, 0, e);
        int d = load_edge(ei, 1, e);
        if ((unsigned)s < NN && (unsigned)d < NN) {
            int pos = g_rowptr[d] + atomicAdd(&g_fill[d], 1);
            float ds = rsqrtf(g_deg[s] + 1.0f);
            float dd = rsqrtf(g_deg[d] + 1.0f);
            g_esrc[pos]  = s;
            g_enorm[pos] = ds * ea[e] * dd;
        }
    }
}

// ----------------------------- FFMA2 SGEMM: C = A[M,Kdim] * B[Kdim,256] ------
// CTA tile 128x64, thread tile 8 rows x 4 cols, K-step 16, double-buffered.
// f32x2 pairs = TWO ADJACENT A ROWS (read pre-paired from smem, zero MOVs);
// B scalar duplicated (4 dup2/k instead of 8). acc[rowpair][col].
__global__ __launch_bounds__(256, 3) void k_gemm2(
    const float* __restrict__ Aext, int use_cat, int cat_off,
    int lda, int Kdim, const float* __restrict__ B)
{
    const float* A = use_cat ? (g_cat + cat_off) : Aext;
    __shared__ __align__(16) float As[2][16][132];   // [k][row], 132 pad
    __shared__ __align__(16) float Bs[2][16][64];
    int tid = threadIdx.x;
    int bm = blockIdx.y, bn = blockIdx.x;
    int tx = tid & 15, ty = tid >> 4;   // tx: col group (4 cols), ty: row group (8 rows)
    uint32_t as_b = smem_u32(As);
    uint32_t bs_b = smem_u32(Bs);

    ull acc2[4][4];   // [rowpair][col]; lo=row ty*8+2i, hi=row ty*8+2i+1
    #pragma unroll
    for (int i = 0; i < 4; i++)
        #pragma unroll
        for (int j = 0; j < 4; j++) acc2[i][j] = 0ull;

    // A tile loads: 512 float4 items; item i: row=i>>2, kq=i&3
    int arow0 = tid >> 2,         akq = tid & 3;
    int arow1 = (256 + tid) >> 2;
    int grow0 = bm * 128 + arow0, grow1 = bm * 128 + arow1;
    bool aok0 = grow0 < NN, aok1 = grow1 < NN;
    // B tile loads: 256 float4 items; item tid: krow=tid>>4, nc=(tid&15)*4
    int bkr = tid >> 4, bnc = (tid & 15) * 4;

    const float* Ap0 = A + (size_t)grow0 * lda + akq * 4;
    const float* Ap1 = A + (size_t)grow1 * lda + akq * 4;
    const float* Bp  = B + (size_t)bkr * HH + bn * 64 + bnc;

    float4 pa0, pa1, pb;
    #define GLOAD(k0)                                                        \
        pa0 = aok0 ? *(const float4*)(Ap0 + (k0)) : make_float4(0.f,0.f,0.f,0.f); \
        pa1 = aok1 ? *(const float4*)(Ap1 + (k0)) : make_float4(0.f,0.f,0.f,0.f); \
        pb  = *(const float4*)(Bp + (size_t)(k0) * HH)
    #define SSTORE(st)                                                       \
        As[st][akq * 4 + 0][arow0] = pa0.x;                                  \
        As[st][akq * 4 + 1][arow0] = pa0.y;                                  \
        As[st][akq * 4 + 2][arow0] = pa0.z;                                  \
        As[st][akq * 4 + 3][arow0] = pa0.w;                                  \
        As[st][akq * 4 + 0][arow1] = pa1.x;                                  \
        As[st][akq * 4 + 1][arow1] = pa1.y;                                  \
        As[st][akq * 4 + 2][arow1] = pa1.z;                                  \
        As[st][akq * 4 + 3][arow1] = pa1.w;                                  \
        *(float4*)&Bs[st][bkr][bnc] = pb

    GLOAD(0);
    SSTORE(0);
    __syncthreads();

    int nC = Kdim >> 4;
    for (int c = 0; c < nC; c++) {
        if (c + 1 < nC) { GLOAD((c + 1) * 16); }      // LDGs overlap FMA block
        int s = c & 1;
        uint32_t abase = as_b + (uint32_t)s * (16 * 132 * 4) + (uint32_t)ty * 32;
        uint32_t bbase = bs_b + (uint32_t)s * 4096 + (uint32_t)tx * 16;
        #pragma unroll
        for (int k = 0; k < 16; k++) {
            ull arp[4];                                // 4 row-pairs, pre-packed
            uint32_t aa = abase + (uint32_t)(k * 528);
            lds128u64(arp[0], arp[1], aa);             // rows +0,+1 | +2,+3
            lds128u64(arp[2], arp[3], aa + 16);        // rows +4,+5 | +6,+7
            float4 bq = *(const float4*)&Bs[s][k][tx * 4];
            ull bd0 = dup2(bq.x), bd1 = dup2(bq.y);
            ull bd2 = dup2(bq.z), bd3 = dup2(bq.w);
            #pragma unroll
            for (int i = 0; i < 4; i++) {
                ffma2(acc2[i][0], arp[i], bd0);
                ffma2(acc2[i][1], arp[i], bd1);
                ffma2(acc2[i][2], arp[i], bd2);
                ffma2(acc2[i][3], arp[i], bd3);
            }
        }
        if (c + 1 < nC) { SSTORE((c + 1) & 1); }
        __syncthreads();
    }
    #undef GLOAD
    #undef SSTORE

    #pragma unroll
    for (int i = 0; i < 4; i++) {
        int row0 = bm * 128 + ty * 8 + 2 * i;
        float lo0, hi0, lo1, hi1, lo2, hi2, lo3, hi3;
        unpack2(lo0, hi0, acc2[i][0]);
        unpack2(lo1, hi1, acc2[i][1]);
        unpack2(lo2, hi2, acc2[i][2]);
        unpack2(lo3, hi3, acc2[i][3]);
        if (row0 < NN)
            *(float4*)(g_xw + (size_t)row0 * HH + bn * 64 + tx * 4) =
                make_float4(lo0, lo1, lo2, lo3);
        if (row0 + 1 < NN)
            *(float4*)(g_xw + (size_t)(row0 + 1) * HH + bn * 64 + tx * 4) =
                make_float4(hi0, hi1, hi2, hi3);
    }
}

// ----------------------------- CSR gather-aggregate + bias + relu -----------
// Lane owns 8 consecutive columns (float4 x2); edge loop unrolled x4 for MLP.
__global__ void k_agg(const float* __restrict__ bias, int out_off, int do_score) {
    int warp = (blockIdx.x * 256 + threadIdx.x) >> 5;
    int lane = threadIdx.x & 31;
    if (warp >= NN) return;
    int n = warp;
    float di = rsqrtf(g_deg[n] + 1.0f);
    float d2 = di * di;
    const float4* xr = (const float4*)(g_xw + (size_t)n * HH);
    float4 v0 = xr[lane * 2], v1 = xr[lane * 2 + 1];
    float4 A0 = make_float4(d2 * v0.x, d2 * v0.y, d2 * v0.z, d2 * v0.w);
    float4 A1 = make_float4(d2 * v1.x, d2 * v1.y, d2 * v1.z, d2 * v1.w);

    int e0 = g_rowptr[n], e1 = g_rowptr[n + 1];
    int e = e0;
    for (; e + 3 < e1; e += 4) {
        int s0 = g_esrc[e],     s1 = g_esrc[e + 1];
        int s2 = g_esrc[e + 2], s3 = g_esrc[e + 3];
        float w0 = g_enorm[e],     w1 = g_enorm[e + 1];
        float w2 = g_enorm[e + 2], w3 = g_enorm[e + 3];
        const float4* r0 = (const float4*)(g_xw + (size_t)s0 * HH);
        const float4* r1 = (const float4*)(g_xw + (size_t)s1 * HH);
        const float4* r2 = (const float4*)(g_xw + (size_t)s2 * HH);
        const float4* r3 = (const float4*)(g_xw + (size_t)s3 * HH);
        float4 p00 = r0[lane * 2], p01 = r0[lane * 2 + 1];
        float4 p10 = r1[lane * 2], p11 = r1[lane * 2 + 1];
        float4 p20 = r2[lane * 2], p21 = r2[lane * 2 + 1];
        float4 p30 = r3[lane * 2], p31 = r3[lane * 2 + 1];
        edge_fma(A0, A1, w0, p00, p01);
        edge_fma(A0, A1, w1, p10, p11);
        edge_fma(A0, A1, w2, p20, p21);
        edge_fma(A0, A1, w3, p30, p31);
    }
    for (; e < e1; e++) {
        int s = g_esrc[e];
        float wgt = g_enorm[e];
        const float4* r0 = (const float4*)(g_xw + (size_t)s * HH);
        float4 p0 = r0[lane * 2], p1 = r0[lane * 2 + 1];
        edge_fma(A0, A1, wgt, p0, p1);
    }
    const float4* b4 = (const float4*)bias;
    float4 B0 = b4[lane * 2], B1 = b4[lane * 2 + 1];
    A0.x = fmaxf(A0.x + B0.x, 0.f); A0.y = fmaxf(A0.y + B0.y, 0.f);
    A0.z = fmaxf(A0.z + B0.z, 0.f); A0.w = fmaxf(A0.w + B0.w, 0.f);
    A1.x = fmaxf(A1.x + B1.x, 0.f); A1.y = fmaxf(A1.y + B1.y, 0.f);
    A1.z = fmaxf(A1.z + B1.z, 0.f); A1.w = fmaxf(A1.w + B1.w, 0.f);
    float4* orow = (float4*)(g_cat + (size_t)n * HH3 + out_off);
    orow[lane * 2]     = A0;
    orow[lane * 2 + 1] = A1;

    if (do_score) {
        const float4* pw4 = (const float4*)g_pwn;
        float4 W0 = pw4[128 + lane * 2], W1 = pw4[128 + lane * 2 + 1];
        float s = A0.x * W0.x;
        s = fmaf(A0.y, W0.y, s); s = fmaf(A0.z, W0.z, s); s = fmaf(A0.w, W0.w, s);
        s = fmaf(A1.x, W1.x, s); s = fmaf(A1.y, W1.y, s);
        s = fmaf(A1.z, W1.z, s); s = fmaf(A1.w, W1.w, s);
        const float4* cr = (const float4*)(g_cat + (size_t)n * HH3);
        #pragma unroll
        for (int j = 0; j < 4; j++) {
            float4 cv = cr[j * 32 + lane];
            float4 pv = pw4[j * 32 + lane];
            s = fmaf(cv.x, pv.x, s); s = fmaf(cv.y, pv.y, s);
            s = fmaf(cv.z, pv.z, s); s = fmaf(cv.w, pv.w, s);
        }
        #pragma unroll
        for (int o = 16; o; o >>= 1) s += __shfl_xor_sync(0xffffffffu, s, o);
        if (lane == 0) g_score[n] = 1.f / (1.f + expf(-s));
    }
}

// ----------------------------- pooling score vector --------------------------
__global__ void k_pwn(const float* __restrict__ pw) {
    __shared__ float red[8];
    __shared__ float s_inv;
    int tid = threadIdx.x;
    float s = 0.f;
    for (int i = tid; i < HH3; i += 256) { float v = pw[i]; s += v * v; }
    #pragma unroll
    for (int o = 16; o; o >>= 1) s += __shfl_xor_sync(0xffffffffu, s, o);
    if ((tid & 31) == 0) red[tid >> 5] = s;
    __syncthreads();
    if (tid == 0) {
        float tot = 0.f;
        for (int i = 0; i < 8; i++) tot += red[i];
        s_inv = rsqrtf(tot);
    }
    __syncthreads();
    for (int i = tid; i < HH3; i += 256) g_pwn[i] = pw[i] * s_inv;
}

// exact top-K selection via rank counting (matches jax top_k tie semantics)
__global__ void k_rank() {
    __shared__ float ss[NPG];
    int g  = blockIdx.x / RANK_BPG;
    int bb = blockIdx.x % RANK_BPG;
    for (int i = threadIdx.x; i < NPG; i += 256) ss[i] = g_score[g * NPG + i];
    __syncthreads();
    int wi = threadIdx.x >> 5, lane = threadIdx.x & 31;
    int i = bb * 8 + wi;
    if (i >= NPG) return;
    float si = ss[i];
    int cnt = 0;
    for (int j0 = 0; j0 < NPG; j0 += 32) {
        int j = j0 + lane;
        bool p = false;
        if (j < NPG) {
            float sj = ss[j];
            p = (sj > si) || (sj == si && j < i);
        }
        cnt += __popc(__ballot_sync(0xffffffffu, p));
    }
    if (lane == 0) g_keep[g * NPG + i] = (cnt < KSEL) ? 1 : 0;
}

// ----------------------------- readout (mean + max over selected) -----------
__global__ void k_readout1() {
    int b  = blockIdx.x;        // b = g*48 + cb*16 + ch
    int g  = b / 48;
    int cb = (b / 16) % 3;
    int ch = b % 16;
    int col = cb * 256 + threadIdx.x;
    int i0 = ch * 391, i1 = min(NPG, i0 + 391);
    float sum = 0.f, mx = -3.402823e38f;
    for (int i = i0; i < i1; i++) {
        int n = g * NPG + i;
        if (g_keep[n]) {
            float s = g_score[n];
            float v = s * g_cat[(size_t)n * HH3 + col];
            sum += v;
            mx = fmaxf(mx, v);
        }
    }
    g_psum[b * 256 + threadIdx.x] = sum;
    g_pmax[b * 256 + threadIdx.x] = mx;
}

__global__ void k_readout2() {
    int b = blockIdx.x;
    int g = b / 3, cb = b % 3;
    int col = cb * 256 + threadIdx.x;
    float sum = 0.f, mx = -3.402823e38f;
    for (int ch = 0; ch < 16; ch++) {
        int idx = ((g * 3 + cb) * 16 + ch) * 256 + threadIdx.x;
        sum += g_psum[idx];
        mx = fmaxf(mx, g_pmax[idx]);
    }
    g_ro[g * 2 * HH3 + col]       = sum * (1.0f / KSEL);
    g_ro[g * 2 * HH3 + HH3 + col] = mx;
}

// ----------------------------- MLP head -------------------------------------
__global__ void k_mlp(const float* __restrict__ lw1, const float* __restrict__ lb1,
                      const float* __restrict__ lw2, const float* __restrict__ lb2,
                      const float* __restrict__ lw3, const float* __restrict__ lb3,
                      float* __restrict__ out) {
    __shared__ float ro[2 * HH3];
    __shared__ float h1[HH];
    __shared__ float h2[HH / 2];
    int g = blockIdx.x, tid = threadIdx.x;
    for (int i = tid; i < 2 * HH3; i += 256) ro[i] = g_ro[g * 2 * HH3 + i];
    __syncthreads();
    float a0 = 0.f, a1 = 0.f, a2 = 0.f, a3 = 0.f;
    for (int k = 0; k < 2 * HH3; k += 4) {
        a0 = fmaf(ro[k + 0], lw1[(k + 0) * HH + tid], a0);
        a1 = fmaf(ro[k + 1], lw1[(k + 1) * HH + tid], a1);
        a2 = fmaf(ro[k + 2], lw1[(k + 2) * HH + tid], a2);
        a3 = fmaf(ro[k + 3], lw1[(k + 3) * HH + tid], a3);
    }
    h1[tid] = fmaxf(a0 + a1 + a2 + a3 + lb1[tid], 0.f);
    __syncthreads();
    if (tid < HH / 2) {
        float b0 = 0.f, b1v = 0.f;
        for (int k = 0; k < HH; k += 2) {
            b0  = fmaf(h1[k],     lw2[k * (HH / 2) + tid],       b0);
            b1v = fmaf(h1[k + 1], lw2[(k + 1) * (HH / 2) + tid], b1v);
        }
        h2[tid] = fmaxf(b0 + b1v + lb2[tid], 0.f);
    }
    __syncthreads();
    if (tid < 3) {
        float s = lb3[tid];
        for (int k = 0; k < HH / 2; k++) s = fmaf(h2[k], lw3[k * 3 + tid], s);
        out[g * 3 + tid] = s;
    }
}

// ----------------------------- launch ---------------------------------------
extern "C" void kernel_launch(void* const* d_in, const int* in_sizes, int n_in,
                              void* d_out, int out_size) {
    const float* x   = (const float*)d_in[0];
    const void*  ei  = d_in[1];              // int32 or int64 (probed at runtime)
    const float* ea  = (const float*)d_in[2];
    // d_in[3] = batch (unused): graph id = node / NPG
    const float* W1  = (const float*)d_in[4];
    const float* b1  = (const float*)d_in[5];
    const float* W2  = (const float*)d_in[6];
    const float* b2  = (const float*)d_in[7];
    const float* pw  = (const float*)d_in[8];
    const float* lw1 = (const float*)d_in[9];
    const float* lb1 = (const float*)d_in[10];
    const float* lw2 = (const float*)d_in[11];
    const float* lb2 = (const float*)d_in[12];
    const float* lw3 = (const float*)d_in[13];
    const float* lb3 = (const float*)d_in[14];
    float* out = (float*)d_out;

    dim3 ggrid(4, (NN + 127) / 128);   // (n-tiles of 64, m-tiles of 128)
    int aggBlocks = (NN + 7) / 8;

    // order keeps gemm1 at launch index 3 so the ncu -s 5 window lands on it
    k_initprobe<<<(NN + 255) / 256, 256>>>((const int*)ei);   // 0
    k_degcnt<<<(EE + 255) / 256, 256>>>(ei, ea);              // 1
    k_pwn<<<1, 256>>>(pw);                                    // 2 (independent)
    k_gemm2<<<ggrid, 256>>>(x, 0, 0, CIN, CIN, W1);           // 3 <- ncu target
    k_scan1<<<49, 1024>>>();                                  // 4
    k_scan2<<<1, 64>>>();                                     // 5
    k_scan3<<<(NN + 255) / 256, 256>>>();                     // 6
    k_fill<<<(EE + 255) / 256, 256>>>(ei, ea);                // 7

    // layer 1 aggregate -> cat[:, 0:256]
    k_agg<<<aggBlocks, 256>>>(b1, 0, 0);
    // layer 2: xw = x1 @ W2 ; x2 -> cat[:, 256:512]
    k_gemm2<<<ggrid, 256>>>(nullptr, 1, 0, HH3, HH, W2);
    k_agg<<<aggBlocks, 256>>>(b2, HH, 0);
    // layer 3: xw = x2 @ W2 ; x3 -> cat[:, 512:768] (+ fused pooling score)
    k_gemm2<<<ggrid, 256>>>(nullptr, 1, HH, HH3, HH, W2);
    k_agg<<<aggBlocks, 256>>>(b2, 2 * HH, 1);

    // pooling
    k_rank<<<BG * RANK_BPG, 256>>>();
    k_readout1<<<384, 256>>>();
    k_readout2<<<24, 256>>>();

    // head
    k_mlp<<<BG, 256>>>(lw1, lb1, lw2, lb2, lw3, lb3, out);
}

// round 16
// speedup vs baseline: 1.1409x; 1.0392x over previous
#include <cuda_runtime.h>
#include <math.h>
#include <stdint.h>

#define NN    50000      // total nodes
#define NPG   6250       // nodes per graph
#define BG    8          // graphs
#define EE    800000     // total edges
#define CIN   512
#define HH    256
#define HH3   768
#define KSEL  5000
#define RANK_BPG 782     // ceil(6250/8) blocks per graph for rank kernel

typedef unsigned long long ull;

// ----------------------------- scratch (static device memory) ---------------
__device__ int   g_is64;
__device__ float g_deg[NN];
__device__ int   g_cnt[NN];
__device__ int   g_rowptr[NN + 1];
__device__ int   g_fill[NN];
__device__ int   g_bsum[64];
__device__ int   g_esrc[EE];
__device__ float g_enorm[EE];
__device__ float g_xw[(size_t)NN * HH];     // 51 MB
__device__ float g_cat[(size_t)NN * HH3];   // 154 MB, [x1|x2|x3]
__device__ float g_score[NN];
__device__ unsigned char g_keep[NN];
__device__ float g_pwn[HH3];
__device__ float g_psum[384 * 256];
__device__ float g_pmax[384 * 256];
__device__ float g_ro[BG * 2 * HH3];

// ----------------------------- f32x2 helpers ---------------------------------
__device__ __forceinline__ uint32_t smem_u32(const void* p) {
    uint32_t a;
    asm("{ .reg .u64 t; cvta.to.shared.u64 t, %1; cvt.u32.u64 %0, t; }" : "=r"(a) : "l"(p));
    return a;
}
__device__ __forceinline__ void ffma2(ull& d, ull a, ull b) {
    asm("fma.rn.f32x2 %0, %1, %2, %0;" : "+l"(d) : "l"(a), "l"(b));
}
__device__ __forceinline__ ull dup2(float x) {
    ull r;
    asm("mov.b64 %0, {%1, %1};" : "=l"(r) : "f"(x));
    return r;
}
__device__ __forceinline__ void lds128u64(ull& a, ull& b, uint32_t addr) {
    asm volatile("ld.shared.v2.u64 {%0,%1}, [%2];" : "=l"(a), "=l"(b) : "r"(addr));
}
__device__ __forceinline__ void unpack2(float& lo, float& hi, ull v) {
    asm("mov.b64 {%0, %1}, %2;" : "=f"(lo), "=f"(hi) : "l"(v));
}
// edge FMA accumulate (function, not macro: avoids token-capture of ".w")
__device__ __forceinline__ void edge_fma(float4& A0, float4& A1, float wgt,
                                         const float4& p0, const float4& p1) {
    A0.x = fmaf(wgt, p0.x, A0.x); A0.y = fmaf(wgt, p0.y, A0.y);
    A0.z = fmaf(wgt, p0.z, A0.z); A0.w = fmaf(wgt, p0.w, A0.w);
    A1.x = fmaf(wgt, p1.x, A1.x); A1.y = fmaf(wgt, p1.y, A1.y);
    A1.z = fmaf(wgt, p1.z, A1.z); A1.w = fmaf(wgt, p1.w, A1.w);
}

// ----------------------------- dtype probe + init -----------------------------
__global__ void k_initprobe(const int* __restrict__ ei32) {
    int i = blockIdx.x * blockDim.x + threadIdx.x;
    if (i < NN) { g_deg[i] = 0.f; g_cnt[i] = 0; g_fill[i] = 0; }
    if (blockIdx.x == 0) {
        __shared__ int nz;
        if (threadIdx.x == 0) nz = 0;
        __syncthreads();
        int any = 0;
        for (int j = 1 + 2 * threadIdx.x; j < 4096; j += 2 * blockDim.x)
            if (ei32[j] != 0) any = 1;
        if (any) atomicAdd(&nz, 1);
        __syncthreads();
        if (threadIdx.x == 0) g_is64 = (nz == 0) ? 1 : 0;
    }
}

__device__ __forceinline__ int load_edge(const void* ei, int which, int e) {
    if (g_is64) return (int)((const long long*)ei)[(size_t)which * EE + e];
    return ((const int*)ei)[which * EE + e];
}

// ----------------------------- setup kernels --------------------------------
__global__ void k_degcnt(const void* __restrict__ ei, const float* __restrict__ ea) {
    int e = blockIdx.x * blockDim.x + threadIdx.x;
    if (e < EE) {
        int d = load_edge(ei, 1, e);
        if ((unsigned)d < NN) {
            atomicAdd(&g_deg[d], ea[e]);
            atomicAdd(&g_cnt[d], 1);
        }
    }
}

__global__ void k_scan1() {
    __shared__ int sm[1024];
    int i = blockIdx.x * 1024 + threadIdx.x;
    int v = (i < NN) ? g_cnt[i] : 0;
    sm[threadIdx.x] = v;
    __syncthreads();
    for (int off = 1; off < 1024; off <<= 1) {
        int t = (threadIdx.x >= off) ? sm[threadIdx.x - off] : 0;
        __syncthreads();
        sm[threadIdx.x] += t;
        __syncthreads();
    }
    if (i < NN) g_rowptr[i] = sm[threadIdx.x] - v;
    if (threadIdx.x == 1023) g_bsum[blockIdx.x] = sm[1023];
}

__global__ void k_scan2() {
    __shared__ int sm[64];
    int t = threadIdx.x;
    int v = (t < 49) ? g_bsum[t] : 0;
    sm[t] = v;
    __syncthreads();
    for (int off = 1; off < 64; off <<= 1) {
        int u = (t >= off) ? sm[t - off] : 0;
        __syncthreads();
        sm[t] += u;
        __syncthreads();
    }
    if (t < 49) g_bsum[t] = sm[t] - v;
}

__global__ void k_scan3() {
    int i = blockIdx.x * blockDim.x + threadIdx.x;
    if (i < NN) g_rowptr[i] += g_bsum[i >> 10];
    if (i == 0) g_rowptr[NN] = EE;
}

__global__ void k_fill(const void* __restrict__ ei, const float* __restrict__ ea) {
    int e = blockIdx.x * blockDim.x + threadIdx.x;
    if (e < EE) {
        int s = load_edge(ei, 0, e);
        int d = load_edge(ei, 1, e);
        if ((unsigned)s < NN && (unsigned)d < NN) {
            int pos = g_rowptr[d] + atomicAdd(&g_fill[d], 1);
            float ds = rsqrtf(g_deg[s] + 1.0f);
            float dd = rsqrtf(g_deg[d] + 1.0f);
            g_esrc[pos]  = s;
            g_enorm[pos] = ds * ea[e] * dd;
        }
    }
}

// ----------------------------- FFMA2 SGEMM: C = A[M,Kdim] * B[Kdim,256] ------
// CTA tile 128x64, thread tile 8 rows x 4 cols, K-step 16, double-buffered smem,
// PREFETCH DISTANCE 2 (two register sets): each chunk's LDGs are issued ~2 chunk
// durations before their SSTORE, covering L2/DRAM latency.
// f32x2 pairs = two adjacent A rows (pre-paired in smem, zero MOVs).
__global__ __launch_bounds__(256, 2) void k_gemm2(
    const float* __restrict__ Aext, int use_cat, int cat_off,
    int lda, int Kdim, const float* __restrict__ B)
{
    const float* A = use_cat ? (g_cat + cat_off) : Aext;
    __shared__ __align__(16) float As[2][16][132];   // [k][row], 132 pad
    __shared__ __align__(16) float Bs[2][16][64];
    int tid = threadIdx.x;
    int bm = blockIdx.y, bn = blockIdx.x;
    int tx = tid & 15, ty = tid >> 4;   // tx: col group (4 cols), ty: row group (8 rows)
    uint32_t as_b = smem_u32(As);
    uint32_t bs_b = smem_u32(Bs);

    ull acc2[4][4];   // [rowpair][col]; lo=row ty*8+2i, hi=row ty*8+2i+1
    #pragma unroll
    for (int i = 0; i < 4; i++)
        #pragma unroll
        for (int j = 0; j < 4; j++) acc2[i][j] = 0ull;

    int arow0 = tid >> 2,         akq = tid & 3;
    int arow1 = (256 + tid) >> 2;
    int grow0 = bm * 128 + arow0, grow1 = bm * 128 + arow1;
    bool aok0 = grow0 < NN, aok1 = grow1 < NN;
    int bkr = tid >> 4, bnc = (tid & 15) * 4;

    const float* Ap0 = A + (size_t)grow0 * lda + akq * 4;
    const float* Ap1 = A + (size_t)grow1 * lda + akq * 4;
    const float* Bp  = B + (size_t)bkr * HH + bn * 64 + bnc;

    float4 pa[2][2], pbr[2];   // two prefetch register sets
    #define GLOAD(set, k0)                                                   \
        pa[set][0] = aok0 ? *(const float4*)(Ap0 + (k0)) : make_float4(0.f,0.f,0.f,0.f); \
        pa[set][1] = aok1 ? *(const float4*)(Ap1 + (k0)) : make_float4(0.f,0.f,0.f,0.f); \
        pbr[set]   = *(const float4*)(Bp + (size_t)(k0) * HH)
    #define SSTORE(st, set)                                                  \
        As[st][akq * 4 + 0][arow0] = pa[set][0].x;                           \
        As[st][akq * 4 + 1][arow0] = pa[set][0].y;                           \
        As[st][akq * 4 + 2][arow0] = pa[set][0].z;                           \
        As[st][akq * 4 + 3][arow0] = pa[set][0].w;                           \
        As[st][akq * 4 + 0][arow1] = pa[set][1].x;                           \
        As[st][akq * 4 + 1][arow1] = pa[set][1].y;                           \
        As[st][akq * 4 + 2][arow1] = pa[set][1].z;                           \
        As[st][akq * 4 + 3][arow1] = pa[set][1].w;                           \
        *(float4*)&Bs[st][bkr][bnc] = pbr[set]

    int nC = Kdim >> 4;   // >= 16 always (K=256 or 512)
    // preload: chunk0 -> smem st0; chunk1 -> set0; chunk2 -> set1
    GLOAD(0, 0);
    SSTORE(0, 0);
    GLOAD(0, 16);          // set0 holds chunk 1
    GLOAD(1, 32);          // set1 holds chunk 2
    __syncthreads();

    for (int c = 0; c < nC; c++) {
        int s = c & 1;
        uint32_t abase = as_b + (uint32_t)s * (16 * 132 * 4) + (uint32_t)ty * 32;
        #pragma unroll
        for (int k = 0; k < 16; k++) {
            ull arp[4];
            uint32_t aa = abase + (uint32_t)(k * 528);
            lds128u64(arp[0], arp[1], aa);
            lds128u64(arp[2], arp[3], aa + 16);
            float4 bq = *(const float4*)&Bs[s][k][tx * 4];
            ull bd0 = dup2(bq.x), bd1 = dup2(bq.y);
            ull bd2 = dup2(bq.z), bd3 = dup2(bq.w);
            #pragma unroll
            for (int i = 0; i < 4; i++) {
                ffma2(acc2[i][0], arp[i], bd0);
                ffma2(acc2[i][1], arp[i], bd1);
                ffma2(acc2[i][2], arp[i], bd2);
                ffma2(acc2[i][3], arp[i], bd3);
            }
        }
        // chunk c+1 was loaded 2 chunks ago into set (c&1); store it, then
        // refill that set with chunk c+3.
        if (c + 1 < nC) {
            if (c & 1) { SSTORE((c + 1) & 1, 1); } else { SSTORE((c + 1) & 1, 0); }
            if (c + 3 < nC) {
                if (c & 1) { GLOAD(1, (c + 3) * 16); } else { GLOAD(0, (c + 3) * 16); }
            }
        }
        __syncthreads();
    }
    #undef GLOAD
    #undef SSTORE

    #pragma unroll
    for (int i = 0; i < 4; i++) {
        int row0 = bm * 128 + ty * 8 + 2 * i;
        float lo0, hi0, lo1, hi1, lo2, hi2, lo3, hi3;
        unpack2(lo0, hi0, acc2[i][0]);
        unpack2(lo1, hi1, acc2[i][1]);
        unpack2(lo2, hi2, acc2[i][2]);
        unpack2(lo3, hi3, acc2[i][3]);
        if (row0 < NN)
            *(float4*)(g_xw + (size_t)row0 * HH + bn * 64 + tx * 4) =
                make_float4(lo0, lo1, lo2, lo3);
        if (row0 + 1 < NN)
            *(float4*)(g_xw + (size_t)(row0 + 1) * HH + bn * 64 + tx * 4) =
                make_float4(hi0, hi1, hi2, hi3);
    }
}

// ----------------------------- CSR gather-aggregate + bias + relu -----------
// Lane owns 8 consecutive columns (float4 x2); edge loop unrolled x4 for MLP.
__global__ void k_agg(const float* __restrict__ bias, int out_off, int do_score) {
    int warp = (blockIdx.x * 256 + threadIdx.x) >> 5;
    int lane = threadIdx.x & 31;
    if (warp >= NN) return;
    int n = warp;
    float di = rsqrtf(g_deg[n] + 1.0f);
    float d2 = di * di;
    const float4* xr = (const float4*)(g_xw + (size_t)n * HH);
    float4 v0 = xr[lane * 2], v1 = xr[lane * 2 + 1];
    float4 A0 = make_float4(d2 * v0.x, d2 * v0.y, d2 * v0.z, d2 * v0.w);
    float4 A1 = make_float4(d2 * v1.x, d2 * v1.y, d2 * v1.z, d2 * v1.w);

    int e0 = g_rowptr[n], e1 = g_rowptr[n + 1];
    int e = e0;
    for (; e + 3 < e1; e += 4) {
        int s0 = g_esrc[e],     s1 = g_esrc[e + 1];
        int s2 = g_esrc[e + 2], s3 = g_esrc[e + 3];
        float w0 = g_enorm[e],     w1 = g_enorm[e + 1];
        float w2 = g_enorm[e + 2], w3 = g_enorm[e + 3];
        const float4* r0 = (const float4*)(g_xw + (size_t)s0 * HH);
        const float4* r1 = (const float4*)(g_xw + (size_t)s1 * HH);
        const float4* r2 = (const float4*)(g_xw + (size_t)s2 * HH);
        const float4* r3 = (const float4*)(g_xw + (size_t)s3 * HH);
        float4 p00 = r0[lane * 2], p01 = r0[lane * 2 + 1];
        float4 p10 = r1[lane * 2], p11 = r1[lane * 2 + 1];
        float4 p20 = r2[lane * 2], p21 = r2[lane * 2 + 1];
        float4 p30 = r3[lane * 2], p31 = r3[lane * 2 + 1];
        edge_fma(A0, A1, w0, p00, p01);
        edge_fma(A0, A1, w1, p10, p11);
        edge_fma(A0, A1, w2, p20, p21);
        edge_fma(A0, A1, w3, p30, p31);
    }
    for (; e < e1; e++) {
        int s = g_esrc[e];
        float wgt = g_enorm[e];
        const float4* r0 = (const float4*)(g_xw + (size_t)s * HH);
        float4 p0 = r0[lane * 2], p1 = r0[lane * 2 + 1];
        edge_fma(A0, A1, wgt, p0, p1);
    }
    const float4* b4 = (const float4*)bias;
    float4 B0 = b4[lane * 2], B1 = b4[lane * 2 + 1];
    A0.x = fmaxf(A0.x + B0.x, 0.f); A0.y = fmaxf(A0.y + B0.y, 0.f);
    A0.z = fmaxf(A0.z + B0.z, 0.f); A0.w = fmaxf(A0.w + B0.w, 0.f);
    A1.x = fmaxf(A1.x + B1.x, 0.f); A1.y = fmaxf(A1.y + B1.y, 0.f);
    A1.z = fmaxf(A1.z + B1.z, 0.f); A1.w = fmaxf(A1.w + B1.w, 0.f);
    float4* orow = (float4*)(g_cat + (size_t)n * HH3 + out_off);
    orow[lane * 2]     = A0;
    orow[lane * 2 + 1] = A1;

    if (do_score) {
        const float4* pw4 = (const float4*)g_pwn;
        float4 W0 = pw4[128 + lane * 2], W1 = pw4[128 + lane * 2 + 1];
        float s = A0.x * W0.x;
        s = fmaf(A0.y, W0.y, s); s = fmaf(A0.z, W0.z, s); s = fmaf(A0.w, W0.w, s);
        s = fmaf(A1.x, W1.x, s); s = fmaf(A1.y, W1.y, s);
        s = fmaf(A1.z, W1.z, s); s = fmaf(A1.w, W1.w, s);
        const float4* cr = (const float4*)(g_cat + (size_t)n * HH3);
        #pragma unroll
        for (int j = 0; j < 4; j++) {
            float4 cv = cr[j * 32 + lane];
            float4 pv = pw4[j * 32 + lane];
            s = fmaf(cv.x, pv.x, s); s = fmaf(cv.y, pv.y, s);
            s = fmaf(cv.z, pv.z, s); s = fmaf(cv.w, pv.w, s);
        }
        #pragma unroll
        for (int o = 16; o; o >>= 1) s += __shfl_xor_sync(0xffffffffu, s, o);
        if (lane == 0) g_score[n] = 1.f / (1.f + expf(-s));
    }
}

// ----------------------------- pooling score vector --------------------------
__global__ void k_pwn(const float* __restrict__ pw) {
    __shared__ float red[8];
    __shared__ float s_inv;
    int tid = threadIdx.x;
    float s = 0.f;
    for (int i = tid; i < HH3; i += 256) { float v = pw[i]; s += v * v; }
    #pragma unroll
    for (int o = 16; o; o >>= 1) s += __shfl_xor_sync(0xffffffffu, s, o);
    if ((tid & 31) == 0) red[tid >> 5] = s;
    __syncthreads();
    if (tid == 0) {
        float tot = 0.f;
        for (int i = 0; i < 8; i++) tot += red[i];
        s_inv = rsqrtf(tot);
    }
    __syncthreads();
    for (int i = tid; i < HH3; i += 256) g_pwn[i] = pw[i] * s_inv;
}

// exact top-K selection via rank counting (matches jax top_k tie semantics)
__global__ void k_rank() {
    __shared__ float ss[NPG];
    int g  = blockIdx.x / RANK_BPG;
    int bb = blockIdx.x % RANK_BPG;
    for (int i = threadIdx.x; i < NPG; i += 256) ss[i] = g_score[g * NPG + i];
    __syncthreads();
    int wi = threadIdx.x >> 5, lane = threadIdx.x & 31;
    int i = bb * 8 + wi;
    if (i >= NPG) return;
    float si = ss[i];
    int cnt = 0;
    for (int j0 = 0; j0 < NPG; j0 += 32) {
        int j = j0 + lane;
        bool p = false;
        if (j < NPG) {
            float sj = ss[j];
            p = (sj > si) || (sj == si && j < i);
        }
        cnt += __popc(__ballot_sync(0xffffffffu, p));
    }
    if (lane == 0) g_keep[g * NPG + i] = (cnt < KSEL) ? 1 : 0;
}

// ----------------------------- readout (mean + max over selected) -----------
__global__ void k_readout1() {
    int b  = blockIdx.x;        // b = g*48 + cb*16 + ch
    int g  = b / 48;
    int cb = (b / 16) % 3;
    int ch = b % 16;
    int col = cb * 256 + threadIdx.x;
    int i0 = ch * 391, i1 = min(NPG, i0 + 391);
    float sum = 0.f, mx = -3.402823e38f;
    for (int i = i0; i < i1; i++) {
        int n = g * NPG + i;
        if (g_keep[n]) {
            float s = g_score[n];
            float v = s * g_cat[(size_t)n * HH3 + col];
            sum += v;
            mx = fmaxf(mx, v);
        }
    }
    g_psum[b * 256 + threadIdx.x] = sum;
    g_pmax[b * 256 + threadIdx.x] = mx;
}

__global__ void k_readout2() {
    int b = blockIdx.x;
    int g = b / 3, cb = b % 3;
    int col = cb * 256 + threadIdx.x;
    float sum = 0.f, mx = -3.402823e38f;
    for (int ch = 0; ch < 16; ch++) {
        int idx = ((g * 3 + cb) * 16 + ch) * 256 + threadIdx.x;
        sum += g_psum[idx];
        mx = fmaxf(mx, g_pmax[idx]);
    }
    g_ro[g * 2 * HH3 + col]       = sum * (1.0f / KSEL);
    g_ro[g * 2 * HH3 + HH3 + col] = mx;
}

// ----------------------------- MLP head -------------------------------------
__global__ void k_mlp(const float* __restrict__ lw1, const float* __restrict__ lb1,
                      const float* __restrict__ lw2, const float* __restrict__ lb2,
                      const float* __restrict__ lw3, const float* __restrict__ lb3,
                      float* __restrict__ out) {
    __shared__ float ro[2 * HH3];
    __shared__ float h1[HH];
    __shared__ float h2[HH / 2];
    int g = blockIdx.x, tid = threadIdx.x;
    for (int i = tid; i < 2 * HH3; i += 256) ro[i] = g_ro[g * 2 * HH3 + i];
    __syncthreads();
    float a0 = 0.f, a1 = 0.f, a2 = 0.f, a3 = 0.f;
    for (int k = 0; k < 2 * HH3; k += 4) {
        a0 = fmaf(ro[k + 0], lw1[(k + 0) * HH + tid], a0);
        a1 = fmaf(ro[k + 1], lw1[(k + 1) * HH + tid], a1);
        a2 = fmaf(ro[k + 2], lw1[(k + 2) * HH + tid], a2);
        a3 = fmaf(ro[k + 3], lw1[(k + 3) * HH + tid], a3);
    }
    h1[tid] = fmaxf(a0 + a1 + a2 + a3 + lb1[tid], 0.f);
    __syncthreads();
    if (tid < HH / 2) {
        float b0 = 0.f, b1v = 0.f;
        for (int k = 0; k < HH; k += 2) {
            b0  = fmaf(h1[k],     lw2[k * (HH / 2) + tid],       b0);
            b1v = fmaf(h1[k + 1], lw2[(k + 1) * (HH / 2) + tid], b1v);
        }
        h2[tid] = fmaxf(b0 + b1v + lb2[tid], 0.f);
    }
    __syncthreads();
    if (tid < 3) {
        float s = lb3[tid];
        for (int k = 0; k < HH / 2; k++) s = fmaf(h2[k], lw3[k * 3 + tid], s);
        out[g * 3 + tid] = s;
    }
}

// ----------------------------- launch ---------------------------------------
extern "C" void kernel_launch(void* const* d_in, const int* in_sizes, int n_in,
                              void* d_out, int out_size) {
    const float* x   = (const float*)d_in[0];
    const void*  ei  = d_in[1];              // int32 or int64 (probed at runtime)
    const float* ea  = (const float*)d_in[2];
    // d_in[3] = batch (unused): graph id = node / NPG
    const float* W1  = (const float*)d_in[4];
    const float* b1  = (const float*)d_in[5];
    const float* W2  = (const float*)d_in[6];
    const float* b2  = (const float*)d_in[7];
    const float* pw  = (const float*)d_in[8];
    const float* lw1 = (const float*)d_in[9];
    const float* lb1 = (const float*)d_in[10];
    const float* lw2 = (const float*)d_in[11];
    const float* lb2 = (const float*)d_in[12];
    const float* lw3 = (const float*)d_in[13];
    const float* lb3 = (const float*)d_in[14];
    float* out = (float*)d_out;

    dim3 ggrid(4, (NN + 127) / 128);   // (n-tiles of 64, m-tiles of 128)
    int aggBlocks = (NN + 7) / 8;

    // order keeps gemm1 at launch index 3 so the ncu -s 5 window lands on it
    k_initprobe<<<(NN + 255) / 256, 256>>>((const int*)ei);   // 0
    k_degcnt<<<(EE + 255) / 256, 256>>>(ei, ea);              // 1
    k_pwn<<<1, 256>>>(pw);                                    // 2 (independent)
    k_gemm2<<<ggrid, 256>>>(x, 0, 0, CIN, CIN, W1);           // 3 <- ncu target
    k_scan1<<<49, 1024>>>();                                  // 4
    k_scan2<<<1, 64>>>();                                     // 5
    k_scan3<<<(NN + 255) / 256, 256>>>();                     // 6
    k_fill<<<(EE + 255) / 256, 256>>>(ei, ea);                // 7

    // layer 1 aggregate -> cat[:, 0:256]
    k_agg<<<aggBlocks, 256>>>(b1, 0, 0);
    // layer 2: xw = x1 @ W2 ; x2 -> cat[:, 256:512]
    k_gemm2<<<ggrid, 256>>>(nullptr, 1, 0, HH3, HH, W2);
    k_agg<<<aggBlocks, 256>>>(b2, HH, 0);
    // layer 3: xw = x2 @ W2 ; x3 -> cat[:, 512:768] (+ fused pooling score)
    k_gemm2<<<ggrid, 256>>>(nullptr, 1, HH, HH3, HH, W2);
    k_agg<<<aggBlocks, 256>>>(b2, 2 * HH, 1);

    // pooling
    k_rank<<<BG * RANK_BPG, 256>>>();
    k_readout1<<<384, 256>>>();
    k_readout2<<<24, 256>>>();

    // head
    k_mlp<<<BG, 256>>>(lw1, lb1, lw2, lb2, lw3, lb3, out);
}

// round 17
// speedup vs baseline: 1.1554x; 1.0127x over previous
#include <cuda_runtime.h>
#include <math.h>
#include <stdint.h>

#define NN    50000      // total nodes
#define NPG   6250       // nodes per graph
#define BG    8          // graphs
#define EE    800000     // total edges
#define CIN   512
#define HH    256
#define HH3   768
#define KSEL  5000
#define RANK_BPG 782     // ceil(6250/8) blocks per graph for rank kernel

typedef unsigned long long ull;

// ----------------------------- scratch (static device memory) ---------------
__device__ int   g_is64;
__device__ float g_deg[NN];
__device__ int   g_cnt[NN];
__device__ int   g_rowptr[NN + 1];
__device__ int   g_fill[NN];
__device__ int   g_bsum[64];
__device__ int   g_esrc[EE];
__device__ float g_enorm[EE];
__device__ float g_xw[(size_t)NN * HH];     // 51 MB
__device__ float g_cat[(size_t)NN * HH3];   // 154 MB, [x1|x2|x3]
__device__ float g_score[NN];
__device__ unsigned char g_keep[NN];
__device__ float g_pwn[HH3];
__device__ float g_psum[384 * 256];
__device__ float g_pmax[384 * 256];
__device__ float g_ro[BG * 2 * HH3];

// ----------------------------- f32x2 helpers ---------------------------------
__device__ __forceinline__ uint32_t smem_u32(const void* p) {
    uint32_t a;
    asm("{ .reg .u64 t; cvta.to.shared.u64 t, %1; cvt.u32.u64 %0, t; }" : "=r"(a) : "l"(p));
    return a;
}
__device__ __forceinline__ void ffma2(ull& d, ull a, ull b) {
    asm("fma.rn.f32x2 %0, %1, %2, %0;" : "+l"(d) : "l"(a), "l"(b));
}
__device__ __forceinline__ ull dup2(float x) {
    ull r;
    asm("mov.b64 %0, {%1, %1};" : "=l"(r) : "f"(x));
    return r;
}
__device__ __forceinline__ void lds128u64(ull& a, ull& b, uint32_t addr) {
    asm volatile("ld.shared.v2.u64 {%0,%1}, [%2];" : "=l"(a), "=l"(b) : "r"(addr));
}
__device__ __forceinline__ void unpack2(float& lo, float& hi, ull v) {
    asm("mov.b64 {%0, %1}, %2;" : "=f"(lo), "=f"(hi) : "l"(v));
}
// edge FMA accumulate (function, not macro: avoids token-capture of ".w")
__device__ __forceinline__ void edge_fma(float4& A0, float4& A1, float wgt,
                                         const float4& p0, const float4& p1) {
    A0.x = fmaf(wgt, p0.x, A0.x); A0.y = fmaf(wgt, p0.y, A0.y);
    A0.z = fmaf(wgt, p0.z, A0.z); A0.w = fmaf(wgt, p0.w, A0.w);
    A1.x = fmaf(wgt, p1.x, A1.x); A1.y = fmaf(wgt, p1.y, A1.y);
    A1.z = fmaf(wgt, p1.z, A1.z); A1.w = fmaf(wgt, p1.w, A1.w);
}

// ----------------------------- dtype probe + init -----------------------------
__global__ void k_initprobe(const int* __restrict__ ei32) {
    int i = blockIdx.x * blockDim.x + threadIdx.x;
    if (i < NN) { g_deg[i] = 0.f; g_cnt[i] = 0; g_fill[i] = 0; }
    if (blockIdx.x == 0) {
        __shared__ int nz;
        if (threadIdx.x == 0) nz = 0;
        __syncthreads();
        int any = 0;
        for (int j = 1 + 2 * threadIdx.x; j < 4096; j += 2 * blockDim.x)
            if (ei32[j] != 0) any = 1;
        if (any) atomicAdd(&nz, 1);
        __syncthreads();
        if (threadIdx.x == 0) g_is64 = (nz == 0) ? 1 : 0;
    }
}

__device__ __forceinline__ int load_edge(const void* ei, int which, int e) {
    if (g_is64) return (int)((const long long*)ei)[(size_t)which * EE + e];
    return ((const int*)ei)[which * EE + e];
}

// ----------------------------- setup kernels --------------------------------
__global__ void k_degcnt(const void* __restrict__ ei, const float* __restrict__ ea) {
    int e = blockIdx.x * blockDim.x + threadIdx.x;
    if (e < EE) {
        int d = load_edge(ei, 1, e);
        if ((unsigned)d < NN) {
            atomicAdd(&g_deg[d], ea[e]);
            atomicAdd(&g_cnt[d], 1);
        }
    }
}

__global__ void k_scan1() {
    __shared__ int sm[1024];
    int i = blockIdx.x * 1024 + threadIdx.x;
    int v = (i < NN) ? g_cnt[i] : 0;
    sm[threadIdx.x] = v;
    __syncthreads();
    for (int off = 1; off < 1024; off <<= 1) {
        int t = (threadIdx.x >= off) ? sm[threadIdx.x - off] : 0;
        __syncthreads();
        sm[threadIdx.x] += t;
        __syncthreads();
    }
    if (i < NN) g_rowptr[i] = sm[threadIdx.x] - v;
    if (threadIdx.x == 1023) g_bsum[blockIdx.x] = sm[1023];
}

__global__ void k_scan2() {
    __shared__ int sm[64];
    int t = threadIdx.x;
    int v = (t < 49) ? g_bsum[t] : 0;
    sm[t] = v;
    __syncthreads();
    for (int off = 1; off < 64; off <<= 1) {
        int u = (t >= off) ? sm[t - off] : 0;
        __syncthreads();
        sm[t] += u;
        __syncthreads();
    }
    if (t < 49) g_bsum[t] = sm[t] - v;
}

__global__ void k_scan3() {
    int i = blockIdx.x * blockDim.x + threadIdx.x;
    if (i < NN) g_rowptr[i] += g_bsum[i >> 10];
    if (i == 0) g_rowptr[NN] = EE;
}

__global__ void k_fill(const void* __restrict__ ei, const float* __restrict__ ea) {
    int e = blockIdx.x * blockDim.x + threadIdx.x;
    if (e < EE) {
        int s = load_edge(ei, 0, e);
        int d = load_edge(ei, 1, e);
        if ((unsigned)s < NN && (unsigned)d < NN) {
            int pos = g_rowptr[d] + atomicAdd(&g_fill[d], 1);
            float ds = rsqrtf(g_deg[s] + 1.0f);
            float dd = rsqrtf(g_deg[d] + 1.0f);
            g_esrc[pos]  = s;
            g_enorm[pos] = ds * ea[e] * dd;
        }
    }
}

// ----------------------------- FFMA2 SGEMM: C = A[M,Kdim] * B[Kdim,256] ------
// CTA tile 128x64, thread tile 8 rows x 4 cols, K-step 16, double-buffered smem,
// prefetch distance 2 (two register sets). f32x2 pairs = two adjacent A rows.
__global__ __launch_bounds__(256, 2) void k_gemm2(
    const float* __restrict__ Aext, int use_cat, int cat_off,
    int lda, int Kdim, const float* __restrict__ B)
{
    const float* A = use_cat ? (g_cat + cat_off) : Aext;
    __shared__ __align__(16) float As[2][16][132];   // [k][row], 132 pad
    __shared__ __align__(16) float Bs[2][16][64];
    int tid = threadIdx.x;
    int bm = blockIdx.y, bn = blockIdx.x;
    int tx = tid & 15, ty = tid >> 4;
    uint32_t as_b = smem_u32(As);
    uint32_t bs_b = smem_u32(Bs);

    ull acc2[4][4];
    #pragma unroll
    for (int i = 0; i < 4; i++)
        #pragma unroll
        for (int j = 0; j < 4; j++) acc2[i][j] = 0ull;

    int arow0 = tid >> 2,         akq = tid & 3;
    int arow1 = (256 + tid) >> 2;
    int grow0 = bm * 128 + arow0, grow1 = bm * 128 + arow1;
    bool aok0 = grow0 < NN, aok1 = grow1 < NN;
    int bkr = tid >> 4, bnc = (tid & 15) * 4;

    const float* Ap0 = A + (size_t)grow0 * lda + akq * 4;
    const float* Ap1 = A + (size_t)grow1 * lda + akq * 4;
    const float* Bp  = B + (size_t)bkr * HH + bn * 64 + bnc;

    float4 pa[2][2], pbr[2];
    #define GLOAD(set, k0)                                                   \
        pa[set][0] = aok0 ? *(const float4*)(Ap0 + (k0)) : make_float4(0.f,0.f,0.f,0.f); \
        pa[set][1] = aok1 ? *(const float4*)(Ap1 + (k0)) : make_float4(0.f,0.f,0.f,0.f); \
        pbr[set]   = *(const float4*)(Bp + (size_t)(k0) * HH)
    #define SSTORE(st, set)                                                  \
        As[st][akq * 4 + 0][arow0] = pa[set][0].x;                           \
        As[st][akq * 4 + 1][arow0] = pa[set][0].y;                           \
        As[st][akq * 4 + 2][arow0] = pa[set][0].z;                           \
        As[st][akq * 4 + 3][arow0] = pa[set][0].w;                           \
        As[st][akq * 4 + 0][arow1] = pa[set][1].x;                           \
        As[st][akq * 4 + 1][arow1] = pa[set][1].y;                           \
        As[st][akq * 4 + 2][arow1] = pa[set][1].z;                           \
        As[st][akq * 4 + 3][arow1] = pa[set][1].w;                           \
        *(float4*)&Bs[st][bkr][bnc] = pbr[set]

    int nC = Kdim >> 4;
    GLOAD(0, 0);
    SSTORE(0, 0);
    GLOAD(0, 16);          // set0 holds chunk 1
    GLOAD(1, 32);          // set1 holds chunk 2
    __syncthreads();

    for (int c = 0; c < nC; c++) {
        int s = c & 1;
        uint32_t abase = as_b + (uint32_t)s * (16 * 132 * 4) + (uint32_t)ty * 32;
        #pragma unroll
        for (int k = 0; k < 16; k++) {
            ull arp[4];
            uint32_t aa = abase + (uint32_t)(k * 528);
            lds128u64(arp[0], arp[1], aa);
            lds128u64(arp[2], arp[3], aa + 16);
            float4 bq = *(const float4*)&Bs[s][k][tx * 4];
            ull bd0 = dup2(bq.x), bd1 = dup2(bq.y);
            ull bd2 = dup2(bq.z), bd3 = dup2(bq.w);
            #pragma unroll
            for (int i = 0; i < 4; i++) {
                ffma2(acc2[i][0], arp[i], bd0);
                ffma2(acc2[i][1], arp[i], bd1);
                ffma2(acc2[i][2], arp[i], bd2);
                ffma2(acc2[i][3], arp[i], bd3);
            }
        }
        if (c + 1 < nC) {
            if (c & 1) { SSTORE((c + 1) & 1, 1); } else { SSTORE((c + 1) & 1, 0); }
            if (c + 3 < nC) {
                if (c & 1) { GLOAD(1, (c + 3) * 16); } else { GLOAD(0, (c + 3) * 16); }
            }
        }
        __syncthreads();
    }
    #undef GLOAD
    #undef SSTORE

    #pragma unroll
    for (int i = 0; i < 4; i++) {
        int row0 = bm * 128 + ty * 8 + 2 * i;
        float lo0, hi0, lo1, hi1, lo2, hi2, lo3, hi3;
        unpack2(lo0, hi0, acc2[i][0]);
        unpack2(lo1, hi1, acc2[i][1]);
        unpack2(lo2, hi2, acc2[i][2]);
        unpack2(lo3, hi3, acc2[i][3]);
        if (row0 < NN)
            *(float4*)(g_xw + (size_t)row0 * HH + bn * 64 + tx * 4) =
                make_float4(lo0, lo1, lo2, lo3);
        if (row0 + 1 < NN)
            *(float4*)(g_xw + (size_t)(row0 + 1) * HH + bn * 64 + tx * 4) =
                make_float4(hi0, hi1, hi2, hi3);
    }
}

// ----------------------------- CSR gather-aggregate + bias + relu -----------
__global__ void k_agg(const float* __restrict__ bias, int out_off, int do_score) {
    int warp = (blockIdx.x * 256 + threadIdx.x) >> 5;
    int lane = threadIdx.x & 31;
    if (warp >= NN) return;
    int n = warp;
    float di = rsqrtf(g_deg[n] + 1.0f);
    float d2 = di * di;
    const float4* xr = (const float4*)(g_xw + (size_t)n * HH);
    float4 v0 = xr[lane * 2], v1 = xr[lane * 2 + 1];
    float4 A0 = make_float4(d2 * v0.x, d2 * v0.y, d2 * v0.z, d2 * v0.w);
    float4 A1 = make_float4(d2 * v1.x, d2 * v1.y, d2 * v1.z, d2 * v1.w);

    int e0 = g_rowptr[n], e1 = g_rowptr[n + 1];
    int e = e0;
    for (; e + 3 < e1; e += 4) {
        int s0 = g_esrc[e],     s1 = g_esrc[e + 1];
        int s2 = g_esrc[e + 2], s3 = g_esrc[e + 3];
        float w0 = g_enorm[e],     w1 = g_enorm[e + 1];
        float w2 = g_enorm[e + 2], w3 = g_enorm[e + 3];
        const float4* r0 = (const float4*)(g_xw + (size_t)s0 * HH);
        const float4* r1 = (const float4*)(g_xw + (size_t)s1 * HH);
        const float4* r2 = (const float4*)(g_xw + (size_t)s2 * HH);
        const float4* r3 = (const float4*)(g_xw + (size_t)s3 * HH);
        float4 p00 = r0[lane * 2], p01 = r0[lane * 2 + 1];
        float4 p10 = r1[lane * 2], p11 = r1[lane * 2 + 1];
        float4 p20 = r2[lane * 2], p21 = r2[lane * 2 + 1];
        float4 p30 = r3[lane * 2], p31 = r3[lane * 2 + 1];
        edge_fma(A0, A1, w0, p00, p01);
        edge_fma(A0, A1, w1, p10, p11);
        edge_fma(A0, A1, w2, p20, p21);
        edge_fma(A0, A1, w3, p30, p31);
    }
    for (; e < e1; e++) {
        int s = g_esrc[e];
        float wgt = g_enorm[e];
        const float4* r0 = (const float4*)(g_xw + (size_t)s * HH);
        float4 p0 = r0[lane * 2], p1 = r0[lane * 2 + 1];
        edge_fma(A0, A1, wgt, p0, p1);
    }
    const float4* b4 = (const float4*)bias;
    float4 B0 = b4[lane * 2], B1 = b4[lane * 2 + 1];
    A0.x = fmaxf(A0.x + B0.x, 0.f); A0.y = fmaxf(A0.y + B0.y, 0.f);
    A0.z = fmaxf(A0.z + B0.z, 0.f); A0.w = fmaxf(A0.w + B0.w, 0.f);
    A1.x = fmaxf(A1.x + B1.x, 0.f); A1.y = fmaxf(A1.y + B1.y, 0.f);
    A1.z = fmaxf(A1.z + B1.z, 0.f); A1.w = fmaxf(A1.w + B1.w, 0.f);
    float4* orow = (float4*)(g_cat + (size_t)n * HH3 + out_off);
    orow[lane * 2]     = A0;
    orow[lane * 2 + 1] = A1;

    if (do_score) {
        const float4* pw4 = (const float4*)g_pwn;
        float4 W0 = pw4[128 + lane * 2], W1 = pw4[128 + lane * 2 + 1];
        float s = A0.x * W0.x;
        s = fmaf(A0.y, W0.y, s); s = fmaf(A0.z, W0.z, s); s = fmaf(A0.w, W0.w, s);
        s = fmaf(A1.x, W1.x, s); s = fmaf(A1.y, W1.y, s);
        s = fmaf(A1.z, W1.z, s); s = fmaf(A1.w, W1.w, s);
        const float4* cr = (const float4*)(g_cat + (size_t)n * HH3);
        #pragma unroll
        for (int j = 0; j < 4; j++) {
            float4 cv = cr[j * 32 + lane];
            float4 pv = pw4[j * 32 + lane];
            s = fmaf(cv.x, pv.x, s); s = fmaf(cv.y, pv.y, s);
            s = fmaf(cv.z, pv.z, s); s = fmaf(cv.w, pv.w, s);
        }
        #pragma unroll
        for (int o = 16; o; o >>= 1) s += __shfl_xor_sync(0xffffffffu, s, o);
        if (lane == 0) g_score[n] = 1.f / (1.f + expf(-s));
    }
}

// ----------------------------- pooling score vector --------------------------
__global__ void k_pwn(const float* __restrict__ pw) {
    __shared__ float red[8];
    __shared__ float s_inv;
    int tid = threadIdx.x;
    float s = 0.f;
    for (int i = tid; i < HH3; i += 256) { float v = pw[i]; s += v * v; }
    #pragma unroll
    for (int o = 16; o; o >>= 1) s += __shfl_xor_sync(0xffffffffu, s, o);
    if ((tid & 31) == 0) red[tid >> 5] = s;
    __syncthreads();
    if (tid == 0) {
        float tot = 0.f;
        for (int i = 0; i < 8; i++) tot += red[i];
        s_inv = rsqrtf(tot);
    }
    __syncthreads();
    for (int i = tid; i < HH3; i += 256) g_pwn[i] = pw[i] * s_inv;
}

// exact top-K selection via rank counting (matches jax top_k tie semantics)
__global__ void k_rank() {
    __shared__ float ss[NPG];
    int g  = blockIdx.x / RANK_BPG;
    int bb = blockIdx.x % RANK_BPG;
    for (int i = threadIdx.x; i < NPG; i += 256) ss[i] = g_score[g * NPG + i];
    __syncthreads();
    int wi = threadIdx.x >> 5, lane = threadIdx.x & 31;
    int i = bb * 8 + wi;
    if (i >= NPG) return;
    float si = ss[i];
    int cnt = 0;
    for (int j0 = 0; j0 < NPG; j0 += 32) {
        int j = j0 + lane;
        bool p = false;
        if (j < NPG) {
            float sj = ss[j];
            p = (sj > si) || (sj == si && j < i);
        }
        cnt += __popc(__ballot_sync(0xffffffffu, p));
    }
    if (lane == 0) g_keep[g * NPG + i] = (cnt < KSEL) ? 1 : 0;
}

// ----------------------------- readout (mean + max over selected) -----------
__global__ void k_readout1() {
    int b  = blockIdx.x;        // b = g*48 + cb*16 + ch
    int g  = b / 48;
    int cb = (b / 16) % 3;
    int ch = b % 16;
    int col = cb * 256 + threadIdx.x;
    int i0 = ch * 391, i1 = min(NPG, i0 + 391);
    float sum = 0.f, mx = -3.402823e38f;
    for (int i = i0; i < i1; i++) {
        int n = g * NPG + i;
        if (g_keep[n]) {
            float s = g_score[n];
            float v = s * g_cat[(size_t)n * HH3 + col];
            sum += v;
            mx = fmaxf(mx, v);
        }
    }
    g_psum[b * 256 + threadIdx.x] = sum;
    g_pmax[b * 256 + threadIdx.x] = mx;
}

__global__ void k_readout2() {
    int b = blockIdx.x;
    int g = b / 3, cb = b % 3;
    int col = cb * 256 + threadIdx.x;
    float sum = 0.f, mx = -3.402823e38f;
    for (int ch = 0; ch < 16; ch++) {
        int idx = ((g * 3 + cb) * 16 + ch) * 256 + threadIdx.x;
        sum += g_psum[idx];
        mx = fmaxf(mx, g_pmax[idx]);
    }
    g_ro[g * 2 * HH3 + col]       = sum * (1.0f / KSEL);
    g_ro[g * 2 * HH3 + HH3 + col] = mx;
}

// ----------------------------- MLP head -------------------------------------
__global__ void k_mlp(const float* __restrict__ lw1, const float* __restrict__ lb1,
                      const float* __restrict__ lw2, const float* __restrict__ lb2,
                      const float* __restrict__ lw3, const float* __restrict__ lb3,
                      float* __restrict__ out) {
    __shared__ float ro[2 * HH3];
    __shared__ float h1[HH];
    __shared__ float h2[HH / 2];
    int g = blockIdx.x, tid = threadIdx.x;
    for (int i = tid; i < 2 * HH3; i += 256) ro[i] = g_ro[g * 2 * HH3 + i];
    __syncthreads();
    float a0 = 0.f, a1 = 0.f, a2 = 0.f, a3 = 0.f;
    for (int k = 0; k < 2 * HH3; k += 4) {
        a0 = fmaf(ro[k + 0], lw1[(k + 0) * HH + tid], a0);
        a1 = fmaf(ro[k + 1], lw1[(k + 1) * HH + tid], a1);
        a2 = fmaf(ro[k + 2], lw1[(k + 2) * HH + tid], a2);
        a3 = fmaf(ro[k + 3], lw1[(k + 3) * HH + tid], a3);
    }
    h1[tid] = fmaxf(a0 + a1 + a2 + a3 + lb1[tid], 0.f);
    __syncthreads();
    if (tid < HH / 2) {
        float b0 = 0.f, b1v = 0.f;
        for (int k = 0; k < HH; k += 2) {
            b0  = fmaf(h1[k],     lw2[k * (HH / 2) + tid],       b0);
            b1v = fmaf(h1[k + 1], lw2[(k + 1) * (HH / 2) + tid], b1v);
        }
        h2[tid] = fmaxf(b0 + b1v + lb2[tid], 0.f);
    }
    __syncthreads();
    if (tid < 3) {
        float s = lb3[tid];
        for (int k = 0; k < HH / 2; k++) s = fmaf(h2[k], lw3[k * 3 + tid], s);
        out[g * 3 + tid] = s;
    }
}

// ----------------------------- launch ---------------------------------------
extern "C" void kernel_launch(void* const* d_in, const int* in_sizes, int n_in,
                              void* d_out, int out_size) {
    const float* x   = (const float*)d_in[0];
    const void*  ei  = d_in[1];              // int32 or int64 (probed at runtime)
    const float* ea  = (const float*)d_in[2];
    // d_in[3] = batch (unused): graph id = node / NPG
    const float* W1  = (const float*)d_in[4];
    const float* b1  = (const float*)d_in[5];
    const float* W2  = (const float*)d_in[6];
    const float* b2  = (const float*)d_in[7];
    const float* pw  = (const float*)d_in[8];
    const float* lw1 = (const float*)d_in[9];
    const float* lb1 = (const float*)d_in[10];
    const float* lw2 = (const float*)d_in[11];
    const float* lb2 = (const float*)d_in[12];
    const float* lw3 = (const float*)d_in[13];
    const float* lb3 = (const float*)d_in[14];
    float* out = (float*)d_out;

    // one-time host resources (created at first, uncaptured call; reused after —
    // identical submitted work on every call)
    static cudaStream_t s2 = []() {
        cudaStream_t s;
        cudaStreamCreateWithFlags(&s, cudaStreamNonBlocking);
        return s;
    }();
    static cudaEvent_t ev0 = []() {
        cudaEvent_t e;
        cudaEventCreateWithFlags(&e, cudaEventDisableTiming);
        return e;
    }();
    static cudaEvent_t ev1 = []() {
        cudaEvent_t e;
        cudaEventCreateWithFlags(&e, cudaEventDisableTiming);
        return e;
    }();

    dim3 ggrid(4, (NN + 127) / 128);   // (n-tiles of 64, m-tiles of 128)
    int aggBlocks = (NN + 7) / 8;

    // fork: CSR build chain on s2, concurrent with gemm1 on the main stream
    cudaEventRecord(ev0, 0);
    cudaStreamWaitEvent(s2, ev0, 0);

    k_initprobe<<<(NN + 255) / 256, 256, 0, s2>>>((const int*)ei);
    k_pwn<<<1, 256, 0, s2>>>(pw);
    k_gemm2<<<ggrid, 256>>>(x, 0, 0, CIN, CIN, W1);       // main stream, concurrent
    k_degcnt<<<(EE + 255) / 256, 256, 0, s2>>>(ei, ea);   // overall launch #6: ncu target
    k_scan1<<<49, 1024, 0, s2>>>();
    k_scan2<<<1, 64, 0, s2>>>();
    k_scan3<<<(NN + 255) / 256, 256, 0, s2>>>();
    k_fill<<<(EE + 255) / 256, 256, 0, s2>>>(ei, ea);

    cudaEventRecord(ev1, s2);
    cudaStreamWaitEvent(0, ev1, 0);    // join: main waits for CSR chain

    // layer 1 aggregate -> cat[:, 0:256]
    k_agg<<<aggBlocks, 256>>>(b1, 0, 0);
    // layer 2: xw = x1 @ W2 ; x2 -> cat[:, 256:512]
    k_gemm2<<<ggrid, 256>>>(nullptr, 1, 0, HH3, HH, W2);
    k_agg<<<aggBlocks, 256>>>(b2, HH, 0);
    // layer 3: xw = x2 @ W2 ; x3 -> cat[:, 512:768] (+ fused pooling score)
    k_gemm2<<<ggrid, 256>>>(nullptr, 1, HH, HH3, HH, W2);
    k_agg<<<aggBlocks, 256>>>(b2, 2 * HH, 1);

    // pooling
    k_rank<<<BG * RANK_BPG, 256>>>();
    k_readout1<<<384, 256>>>();
    k_readout2<<<24, 256>>>();

    // head
    k_mlp<<<BG, 256>>>(lw1, lb1, lw2, lb2, lw3, lb3, out);
}